// round 1
// baseline (speedup 1.0000x reference)
#include <cuda_runtime.h>
#include <math.h>
#include <math_constants.h>

#define BB 4
#define SS 2048
#define DM 1024
#define HH 16
#define DKK 64
#define MTOT (BB*SS)   // 8192

// Scratch (allocation-free per harness rules)
__device__ float g_Q[BB*HH*SS*DKK];
__device__ float g_K[BB*HH*SS*DKK];
__device__ float g_V[BB*HH*SS*DKK];
__device__ float g_AO[(size_t)BB*SS*DM];

// ---------------------------------------------------------------------------
// GEMM: C[m,e] = sum_d A[m,d] * W[e,d]   (M=8192, N=1024, K=1024)
// mode 0: RoPE -> g_Q [b,h,s,dk]; mode 1: RoPE -> g_K; mode 2: copy -> g_V;
// mode 3: plain -> out[m,e]
// Block tile 128x128, BK=16, 256 threads, 8x8 per thread.
// ---------------------------------------------------------------------------
__global__ __launch_bounds__(256, 2)
void gemm_kernel(const float* __restrict__ A, const float* __restrict__ W,
                 float* __restrict__ out, const int* __restrict__ tokpos,
                 int mode)
{
    __shared__ float As[16][128];
    __shared__ float Bs[16][128];

    const int tid = threadIdx.x;
    const int tx = tid & 15;
    const int ty = tid >> 4;
    const int m0 = blockIdx.x * 128;
    const int n0 = blockIdx.y * 128;

    float acc[8][8];
#pragma unroll
    for (int i = 0; i < 8; i++)
#pragma unroll
        for (int j = 0; j < 8; j++) acc[i][j] = 0.f;

    for (int k0 = 0; k0 < DM; k0 += 16) {
#pragma unroll
        for (int it = 0; it < 2; it++) {
            int f = tid + it * 256;          // 0..511
            int row  = f >> 2;               // 0..127
            int kseg = (f & 3) << 2;         // 0,4,8,12
            float4 va = *(const float4*)&A[(size_t)(m0 + row) * DM + k0 + kseg];
            As[kseg + 0][row] = va.x; As[kseg + 1][row] = va.y;
            As[kseg + 2][row] = va.z; As[kseg + 3][row] = va.w;
            float4 vb = *(const float4*)&W[(size_t)(n0 + row) * DM + k0 + kseg];
            Bs[kseg + 0][row] = vb.x; Bs[kseg + 1][row] = vb.y;
            Bs[kseg + 2][row] = vb.z; Bs[kseg + 3][row] = vb.w;
        }
        __syncthreads();
#pragma unroll
        for (int kk = 0; kk < 16; kk++) {
            float a[8], b[8];
            *(float4*)&a[0] = *(const float4*)&As[kk][ty * 8];
            *(float4*)&a[4] = *(const float4*)&As[kk][ty * 8 + 4];
            *(float4*)&b[0] = *(const float4*)&Bs[kk][tx * 8];
            *(float4*)&b[4] = *(const float4*)&Bs[kk][tx * 8 + 4];
#pragma unroll
            for (int i = 0; i < 8; i++)
#pragma unroll
                for (int j = 0; j < 8; j++) acc[i][j] += a[i] * b[j];
        }
        __syncthreads();
    }

    const int m_base = m0 + ty * 8;
    const int e_base = n0 + tx * 8;

    if (mode == 3) {
#pragma unroll
        for (int i = 0; i < 8; i++) {
            float* p = &out[(size_t)(m_base + i) * DM + e_base];
            *(float4*)&p[0] = *(float4*)&acc[i][0];
            *(float4*)&p[4] = *(float4*)&acc[i][4];
        }
        return;
    }

    const int h   = e_base >> 6;      // all 8 columns share one head (e_base%64<=56)
    const int dk0 = e_base & 63;

    if (mode == 2) {   // V: plain reshape to [b,h,s,dk]
#pragma unroll
        for (int i = 0; i < 8; i++) {
            int m = m_base + i;
            int b = m / SS, s = m % SS;
            float* p = &out[((size_t)(b * HH + h) * SS + s) * DKK + dk0];
            *(float4*)&p[0] = *(float4*)&acc[i][0];
            *(float4*)&p[4] = *(float4*)&acc[i][4];
        }
        return;
    }

    // modes 0/1: RoPE. pair index for column pair p: ipair = dk0/2 + p
    // inv_freq = 10000^(-ipair/32) computed in double for accuracy.
    float fr[4];
#pragma unroll
    for (int p = 0; p < 4; p++) {
        int ipair = (dk0 >> 1) + p;
        fr[p] = (float)exp2(-(double)ipair * (13.287712379549449 / 32.0));
    }
#pragma unroll
    for (int i = 0; i < 8; i++) {
        int m = m_base + i;
        int b = m / SS, s = m % SS;
        float pos = (float)tokpos[s];
        float r[8];
#pragma unroll
        for (int p = 0; p < 4; p++) {
            float ang = pos * fr[p];
            float sn, cs;
            sincosf(ang, &sn, &cs);
            float x1 = acc[i][2 * p + 0];
            float x2 = acc[i][2 * p + 1];
            r[2 * p + 0] = x1 * cs - x2 * sn;
            r[2 * p + 1] = x1 * sn + x2 * cs;
        }
        float* pdst = &out[((size_t)(b * HH + h) * SS + s) * DKK + dk0];
        *(float4*)&pdst[0] = *(float4*)&r[0];
        *(float4*)&pdst[4] = *(float4*)&r[4];
    }
}

// ---------------------------------------------------------------------------
// Flash attention (fp32, causal). One block = 128 query rows of one (b,h).
// 256 threads as 16x16; per-thread 8x4 tiles. Online softmax in exp2 domain.
// smem: Qs[128][64], Kst[64][68] (k-major transposed), Vs[64][68], Ps[64][129]
// ---------------------------------------------------------------------------
#define RK 68
#define RP 129
#define SMEM_FLOATS (128*64 + 64*RK + 64*RK + 64*RP)

__global__ __launch_bounds__(256, 1)
void attn_kernel(const float* __restrict__ Q, const float* __restrict__ K,
                 const float* __restrict__ V, float* __restrict__ O)
{
    extern __shared__ float sm[];
    float* Qs  = sm;                       // [128][64]
    float* Kst = Qs + 128 * 64;            // [64][RK]  (Kst[k*RK + j])
    float* Vs  = Kst + 64 * RK;            // [64][RK]  (Vs[j*RK + d])
    float* Ps  = Vs + 64 * RK;             // [64][RP]  (Ps[j*RP + r])

    const int tid = threadIdx.x;
    const int tx = tid & 15;
    const int ty = tid >> 4;
    const int bh = blockIdx.y;
    const int qb = gridDim.x - 1 - blockIdx.x;   // heavy blocks first
    const size_t base = (size_t)bh * SS * DKK;

    const float QSCALE = 0.125f * 1.4426950408889634f;  // 1/sqrt(64) * log2(e)

    // Load + pre-scale Q tile
#pragma unroll
    for (int it = 0; it < 8; it++) {
        int f = tid + it * 256;            // 0..2047
        int r  = f >> 4;
        int c4 = (f & 15) << 2;
        float4 v = *(const float4*)&Q[base + (size_t)(qb * 128 + r) * DKK + c4];
        v.x *= QSCALE; v.y *= QSCALE; v.z *= QSCALE; v.w *= QSCALE;
        *(float4*)&Qs[r * 64 + c4] = v;
    }

    float acc[8][4];
    float m_i[8], l_i[8];
#pragma unroll
    for (int i = 0; i < 8; i++) {
        m_i[i] = -CUDART_INF_F; l_i[i] = 0.f;
        acc[i][0] = acc[i][1] = acc[i][2] = acc[i][3] = 0.f;
    }

    int qr[8];
#pragma unroll
    for (int i = 0; i < 8; i++) qr[i] = qb * 128 + ty * 8 + i;

    const int kb_end = 2 * qb + 2;
    for (int kb = 0; kb < kb_end; kb++) {
        __syncthreads();   // protect smem reuse (also covers Qs on first iter)
#pragma unroll
        for (int it = 0; it < 4; it++) {
            int f = tid + it * 256;        // 0..1023
            int j  = f >> 4;
            int c4 = (f & 15) << 2;
            float4 kv = *(const float4*)&K[base + (size_t)(kb * 64 + j) * DKK + c4];
            Kst[(c4 + 0) * RK + j] = kv.x;
            Kst[(c4 + 1) * RK + j] = kv.y;
            Kst[(c4 + 2) * RK + j] = kv.z;
            Kst[(c4 + 3) * RK + j] = kv.w;
            float4 vv = *(const float4*)&V[base + (size_t)(kb * 64 + j) * DKK + c4];
            *(float4*)&Vs[j * RK + c4] = vv;
        }
        __syncthreads();

        // S tile: st[i][j] = (Q . K) (already scaled & in log2 units)
        float st[8][4];
#pragma unroll
        for (int i = 0; i < 8; i++)
            st[i][0] = st[i][1] = st[i][2] = st[i][3] = 0.f;

        for (int k4 = 0; k4 < 64; k4 += 4) {
            float4 b0 = *(const float4*)&Kst[(k4 + 0) * RK + tx * 4];
            float4 b1 = *(const float4*)&Kst[(k4 + 1) * RK + tx * 4];
            float4 b2 = *(const float4*)&Kst[(k4 + 2) * RK + tx * 4];
            float4 b3 = *(const float4*)&Kst[(k4 + 3) * RK + tx * 4];
#pragma unroll
            for (int i = 0; i < 8; i++) {
                float4 a = *(const float4*)&Qs[(ty * 8 + i) * 64 + k4];
                st[i][0] += a.x * b0.x + a.y * b1.x + a.z * b2.x + a.w * b3.x;
                st[i][1] += a.x * b0.y + a.y * b1.y + a.z * b2.y + a.w * b3.y;
                st[i][2] += a.x * b0.z + a.y * b1.z + a.z * b2.z + a.w * b3.z;
                st[i][3] += a.x * b0.w + a.y * b1.w + a.z * b2.w + a.w * b3.w;
            }
        }

        // Causal mask (only near-diagonal key blocks need it)
        if (kb >= 2 * qb) {
#pragma unroll
            for (int i = 0; i < 8; i++) {
#pragma unroll
                for (int j = 0; j < 4; j++) {
                    int kc = kb * 64 + tx * 4 + j;
                    if (kc > qr[i]) st[i][j] = -CUDART_INF_F;
                }
            }
        }

        // Online softmax (base-2)
#pragma unroll
        for (int i = 0; i < 8; i++) {
            float mx = fmaxf(fmaxf(st[i][0], st[i][1]), fmaxf(st[i][2], st[i][3]));
#pragma unroll
            for (int off = 1; off < 16; off <<= 1)
                mx = fmaxf(mx, __shfl_xor_sync(0xffffffffu, mx, off));
            float mnew  = fmaxf(m_i[i], mx);
            float alpha = exp2f(m_i[i] - mnew);
            m_i[i] = mnew;
            float p0 = exp2f(st[i][0] - mnew);
            float p1 = exp2f(st[i][1] - mnew);
            float p2 = exp2f(st[i][2] - mnew);
            float p3 = exp2f(st[i][3] - mnew);
            float rs = (p0 + p1) + (p2 + p3);
#pragma unroll
            for (int off = 1; off < 16; off <<= 1)
                rs += __shfl_xor_sync(0xffffffffu, rs, off);
            l_i[i] = l_i[i] * alpha + rs;
            acc[i][0] *= alpha; acc[i][1] *= alpha;
            acc[i][2] *= alpha; acc[i][3] *= alpha;
            int r = ty * 8 + i;
            Ps[(tx * 4 + 0) * RP + r] = p0;
            Ps[(tx * 4 + 1) * RP + r] = p1;
            Ps[(tx * 4 + 2) * RP + r] = p2;
            Ps[(tx * 4 + 3) * RP + r] = p3;
        }
        __syncthreads();

        // O += P @ V
        for (int j = 0; j < 64; j++) {
            float4 bv = *(const float4*)&Vs[j * RK + tx * 4];
            const float* prow = &Ps[j * RP + ty * 8];
#pragma unroll
            for (int i = 0; i < 8; i++) {
                float p = prow[i];
                acc[i][0] += p * bv.x;
                acc[i][1] += p * bv.y;
                acc[i][2] += p * bv.z;
                acc[i][3] += p * bv.w;
            }
        }
    }

    const int b = bh >> 4;   // /HH
    const int h = bh & 15;
#pragma unroll
    for (int i = 0; i < 8; i++) {
        float inv = 1.0f / l_i[i];
        float4 o;
        o.x = acc[i][0] * inv; o.y = acc[i][1] * inv;
        o.z = acc[i][2] * inv; o.w = acc[i][3] * inv;
        *(float4*)&O[(size_t)(b * SS + qr[i]) * DM + h * DKK + tx * 4] = o;
    }
}

// ---------------------------------------------------------------------------
extern "C" void kernel_launch(void* const* d_in, const int* in_sizes, int n_in,
                              void* d_out, int out_size)
{
    const float* x   = (const float*)d_in[0];
    const float* Wq  = (const float*)d_in[1];
    const float* Wk  = (const float*)d_in[2];
    const float* Wv  = (const float*)d_in[3];
    const float* Wo  = (const float*)d_in[4];
    const int*   tp  = (const int*)  d_in[5];
    float* out = (float*)d_out;

    float *gQ, *gK, *gV, *gAO;
    cudaGetSymbolAddress((void**)&gQ,  g_Q);
    cudaGetSymbolAddress((void**)&gK,  g_K);
    cudaGetSymbolAddress((void**)&gV,  g_V);
    cudaGetSymbolAddress((void**)&gAO, g_AO);

    const int smem_bytes = SMEM_FLOATS * (int)sizeof(float);
    cudaFuncSetAttribute(attn_kernel,
                         cudaFuncAttributeMaxDynamicSharedMemorySize, smem_bytes);

    dim3 ggrid(MTOT / 128, DM / 128);   // 64 x 8
    gemm_kernel<<<ggrid, 256>>>(x, Wq, gQ, tp, 0);
    gemm_kernel<<<ggrid, 256>>>(x, Wk, gK, tp, 1);
    gemm_kernel<<<ggrid, 256>>>(x, Wv, gV, tp, 2);

    dim3 agrid(SS / 128, BB * HH);      // 16 x 64
    attn_kernel<<<agrid, 256, smem_bytes>>>(gQ, gK, gV, gAO);

    gemm_kernel<<<ggrid, 256>>>(gAO, Wo, out, tp, 3);
}

// round 3
// speedup vs baseline: 1.4089x; 1.4089x over previous
#include <cuda_runtime.h>
#include <cuda_bf16.h>
#include <math.h>
#include <math_constants.h>
#include <cstdint>

#define BB 4
#define SS 2048
#define DM 1024
#define HH 16
#define DKK 64
#define MTOT (BB*SS)   // 8192

// ---------------- scratch (allocation-free) ----------------
__device__ __nv_bfloat16 g_xh[(size_t)MTOT*DM],  g_xl[(size_t)MTOT*DM];
__device__ __nv_bfloat16 g_aoh[(size_t)MTOT*DM], g_aol[(size_t)MTOT*DM];
__device__ __nv_bfloat16 g_wh[(size_t)4*DM*DM],  g_wl[(size_t)4*DM*DM];
__device__ float g_Q[(size_t)BB*HH*SS*DKK];
__device__ float g_K[(size_t)BB*HH*SS*DKK];
__device__ float g_V[(size_t)BB*HH*SS*DKK];
__device__ float g_AO[(size_t)BB*SS*DM];
__device__ float g_rope[SS*64];   // [s][0..31]=cos, [s][32..63]=sin

// ---------------- PTX helpers (baseline ISA only, no sm_10xa features) ----
__device__ __forceinline__ uint32_t smem_to_u32(const void* p) {
    uint32_t a;
    asm("{ .reg .u64 t; cvta.to.shared.u64 t, %1; cvt.u32.u64 %0, t; }"
        : "=r"(a) : "l"(p));
    return a;
}
__device__ __forceinline__ void cp16(uint32_t dst, const void* src) {
    asm volatile("cp.async.cg.shared.global [%0], [%1], 16;"
                 :: "r"(dst), "l"(src) : "memory");
}
#define CP_COMMIT() asm volatile("cp.async.commit_group;" ::: "memory")
#define CP_WAIT1()  asm volatile("cp.async.wait_group 1;"  ::: "memory")
#define CP_WAIT0()  asm volatile("cp.async.wait_group 0;"  ::: "memory")

__device__ __forceinline__ void ldsm4(uint32_t* r, uint32_t addr) {
    asm volatile("ldmatrix.sync.aligned.m8n8.x4.shared.b16 {%0,%1,%2,%3}, [%4];"
                 : "=r"(r[0]), "=r"(r[1]), "=r"(r[2]), "=r"(r[3]) : "r"(addr));
}
__device__ __forceinline__ void mma16816(float* d, const uint32_t* a,
                                         uint32_t b0, uint32_t b1) {
    asm volatile("mma.sync.aligned.m16n8k16.row.col.f32.bf16.bf16.f32 "
                 "{%0,%1,%2,%3}, {%4,%5,%6,%7}, {%8,%9}, {%0,%1,%2,%3};"
                 : "+f"(d[0]), "+f"(d[1]), "+f"(d[2]), "+f"(d[3])
                 : "r"(a[0]), "r"(a[1]), "r"(a[2]), "r"(a[3]), "r"(b0), "r"(b1));
}

// ---------------------------------------------------------------------------
// fp32 -> (bf16 hi, bf16 lo) split
// ---------------------------------------------------------------------------
__global__ void split_kernel(const float* __restrict__ src,
                             __nv_bfloat16* __restrict__ hi,
                             __nv_bfloat16* __restrict__ lo, int n4)
{
    int i = blockIdx.x * blockDim.x + threadIdx.x;
    if (i >= n4) return;
    float4 v = ((const float4*)src)[i];
    __nv_bfloat16 h0 = __float2bfloat16(v.x);
    __nv_bfloat16 h1 = __float2bfloat16(v.y);
    __nv_bfloat16 h2 = __float2bfloat16(v.z);
    __nv_bfloat16 h3 = __float2bfloat16(v.w);
    __nv_bfloat16 l0 = __float2bfloat16(v.x - __bfloat162float(h0));
    __nv_bfloat16 l1 = __float2bfloat16(v.y - __bfloat162float(h1));
    __nv_bfloat16 l2 = __float2bfloat16(v.z - __bfloat162float(h2));
    __nv_bfloat16 l3 = __float2bfloat16(v.w - __bfloat162float(h3));
    __nv_bfloat162 ph0 = __halves2bfloat162(h0, h1), ph1 = __halves2bfloat162(h2, h3);
    __nv_bfloat162 pl0 = __halves2bfloat162(l0, l1), pl1 = __halves2bfloat162(l2, l3);
    uint2 uh, ul;
    uh.x = *(uint32_t*)&ph0; uh.y = *(uint32_t*)&ph1;
    ul.x = *(uint32_t*)&pl0; ul.y = *(uint32_t*)&pl1;
    ((uint2*)hi)[i] = uh;
    ((uint2*)lo)[i] = ul;
}

// ---------------------------------------------------------------------------
// RoPE cos/sin table
// ---------------------------------------------------------------------------
__global__ void rope_init_kernel(const int* __restrict__ tokpos, float* __restrict__ rope)
{
    int idx = blockIdx.x * blockDim.x + threadIdx.x;   // 0..65535
    int s = idx >> 5, p = idx & 31;
    float fr = (float)exp2(-(double)p * (13.287712379549449 / 32.0));
    float ang = (float)tokpos[s] * fr;
    float sn, cs;
    sincosf(ang, &sn, &cs);
    rope[s * 64 + p] = cs;
    rope[s * 64 + 32 + p] = sn;
}

// ---------------------------------------------------------------------------
// bf16x3 mma.sync GEMM: C[m,e] = sum_d A[m,d]*W[e,d]  (M=8192,N=1024,K=1024)
// CTA tile 128x128, BK=32, warp grid 4x2 (warp tile 32x64), double-buffered
// cp.async. smem pitch 40 bf16 (80B) => conflict-free ldmatrix.
// mode 0/1: RoPE -> [b,h,s,dk]; mode 2: reshape -> [b,h,s,dk]; mode 3: plain.
// ---------------------------------------------------------------------------
#define GP      40                 // smem pitch (bf16)
#define TILE_B  (128*GP*2)         // 10240 bytes per tile
#define STAGE_B (4*TILE_B)         // Ah|Al|Bh|Bl = 40960
#define GSMEM   (2*STAGE_B)        // 81920

__device__ __forceinline__ void issue_stage(uint32_t sdst,
    const __nv_bfloat16* __restrict__ Ah, const __nv_bfloat16* __restrict__ Al,
    const __nv_bfloat16* __restrict__ Bh, const __nv_bfloat16* __restrict__ Bl,
    int m0, int n0, int kc, int tid)
{
    const int colb = kc * 64;   // byte offset of k-chunk within a row
#pragma unroll
    for (int it = 0; it < 2; it++) {
        int idx = tid + it * 256;
        int row = idx >> 2;
        int ch  = (idx & 3) * 16;
        uint32_t soff = row * 80 + ch;
        const char* pa = (const char*)(Ah + (size_t)(m0 + row) * DM) + colb + ch;
        const char* pl = (const char*)(Al + (size_t)(m0 + row) * DM) + colb + ch;
        const char* pb = (const char*)(Bh + (size_t)(n0 + row) * DM) + colb + ch;
        const char* pc = (const char*)(Bl + (size_t)(n0 + row) * DM) + colb + ch;
        cp16(sdst + 0 * TILE_B + soff, pa);
        cp16(sdst + 1 * TILE_B + soff, pl);
        cp16(sdst + 2 * TILE_B + soff, pb);
        cp16(sdst + 3 * TILE_B + soff, pc);
    }
}

__global__ __launch_bounds__(256, 1)
void gemm_mma(const __nv_bfloat16* __restrict__ Ah, const __nv_bfloat16* __restrict__ Al,
              const __nv_bfloat16* __restrict__ Bh, const __nv_bfloat16* __restrict__ Bl,
              float* __restrict__ out, const float* __restrict__ rope, int mode)
{
    extern __shared__ char smc[];
    const uint32_t sbase = smem_to_u32(smc);

    const int tid  = threadIdx.x;
    const int wid  = tid >> 5;
    const int lane = tid & 31;
    const int m0 = blockIdx.x * 128;
    const int n0 = blockIdx.y * 128;
    const int wm = (wid & 3) * 32;    // warp M offset within CTA
    const int wn = (wid >> 2) * 64;   // warp N offset within CTA

    float acc[2][8][4];
#pragma unroll
    for (int i = 0; i < 2; i++)
#pragma unroll
        for (int j = 0; j < 8; j++)
#pragma unroll
            for (int q = 0; q < 4; q++) acc[i][j][q] = 0.f;

    // ldmatrix lane addressing (same formula for A and B tiles):
    // row-within-16 = (lane&7) + 8*bit3 ; k-half byte = 16*bit4
    const uint32_t lrow = (lane & 7) + ((lane >> 3) & 1) * 8;
    const uint32_t kbl  = ((lane >> 4) & 1) * 16;

    issue_stage(sbase, Ah, Al, Bh, Bl, m0, n0, 0, tid);
    CP_COMMIT();

    const int NKC = DM / 32;   // 32
    for (int kc = 0; kc < NKC; kc++) {
        if (kc + 1 < NKC) {
            issue_stage(sbase + ((kc + 1) & 1) * STAGE_B, Ah, Al, Bh, Bl,
                        m0, n0, kc + 1, tid);
            CP_COMMIT();
            CP_WAIT1();
        } else {
            CP_WAIT0();
        }
        __syncthreads();

        const uint32_t sb = sbase + (kc & 1) * STAGE_B;
#pragma unroll
        for (int ks = 0; ks < 2; ks++) {
            const uint32_t kb = ks * 32 + kbl;
            uint32_t ah0[4], ah1[4], al0[4], al1[4];
            const uint32_t aadr = sb + (wm + lrow) * 80 + kb;
            ldsm4(ah0, aadr);
            ldsm4(ah1, aadr + 16 * 80);
            ldsm4(al0, aadr + TILE_B);
            ldsm4(al1, aadr + TILE_B + 16 * 80);
            uint32_t bh[4][4], bl[4][4];
#pragma unroll
            for (int nb = 0; nb < 4; nb++) {
                const uint32_t badr = sb + 2 * TILE_B + (wn + nb * 16 + lrow) * 80 + kb;
                ldsm4(bh[nb], badr);
                ldsm4(bl[nb], badr + TILE_B);
            }
#pragma unroll
            for (int nj = 0; nj < 8; nj++) {
                const int nb = nj >> 1, sel = nj & 1;
                const uint32_t b0h = bh[nb][sel], b1h = bh[nb][sel + 2];
                const uint32_t b0l = bl[nb][sel], b1l = bl[nb][sel + 2];
                mma16816(acc[0][nj], ah0, b0h, b1h);   // Ah*Bh
                mma16816(acc[1][nj], ah1, b0h, b1h);
                mma16816(acc[0][nj], ah0, b0l, b1l);   // Ah*Bl
                mma16816(acc[1][nj], ah1, b0l, b1l);
                mma16816(acc[0][nj], al0, b0h, b1h);   // Al*Bh
                mma16816(acc[1][nj], al1, b0h, b1h);
            }
        }
        __syncthreads();
    }

    // ---- epilogue ----
    const int g = lane >> 2;
    const int t2 = (lane & 3) * 2;
#pragma unroll
    for (int mi = 0; mi < 2; mi++) {
#pragma unroll
        for (int half = 0; half < 2; half++) {
            const int r = m0 + wm + mi * 16 + half * 8 + g;   // global row
            const int b = r >> 11;
            const int s = r & 2047;
#pragma unroll
            for (int nj = 0; nj < 8; nj++) {
                const int e = n0 + wn + nj * 8 + t2;          // global col (even)
                float d0 = acc[mi][nj][half * 2 + 0];
                float d1 = acc[mi][nj][half * 2 + 1];
                if (mode == 3) {
                    float2 o = make_float2(d0, d1);
                    *(float2*)&out[(size_t)r * DM + e] = o;
                } else {
                    const int h  = e >> 6;
                    const int dk = e & 63;
                    float* dst = &out[((size_t)(b * HH + h) * SS + s) * DKK + dk];
                    if (mode == 2) {
                        *(float2*)dst = make_float2(d0, d1);
                    } else {
                        const int p = dk >> 1;
                        float cs = __ldg(&rope[s * 64 + p]);
                        float sn = __ldg(&rope[s * 64 + 32 + p]);
                        *(float2*)dst = make_float2(d0 * cs - d1 * sn,
                                                    d0 * sn + d1 * cs);
                    }
                }
            }
        }
    }
}

// ---------------------------------------------------------------------------
// Flash attention (fp32, causal) — unchanged (validated round 1).
// ---------------------------------------------------------------------------
#define RK 68
#define RP 129
#define SMEM_FLOATS (128*64 + 64*RK + 64*RK + 64*RP)

__global__ __launch_bounds__(256, 1)
void attn_kernel(const float* __restrict__ Q, const float* __restrict__ K,
                 const float* __restrict__ V, float* __restrict__ O)
{
    extern __shared__ float sm[];
    float* Qs  = sm;
    float* Kst = Qs + 128 * 64;
    float* Vs  = Kst + 64 * RK;
    float* Ps  = Vs + 64 * RK;

    const int tid = threadIdx.x;
    const int tx = tid & 15;
    const int ty = tid >> 4;
    const int bh = blockIdx.y;
    const int qb = gridDim.x - 1 - blockIdx.x;
    const size_t base = (size_t)bh * SS * DKK;

    const float QSCALE = 0.125f * 1.4426950408889634f;

#pragma unroll
    for (int it = 0; it < 8; it++) {
        int f = tid + it * 256;
        int r  = f >> 4;
        int c4 = (f & 15) << 2;
        float4 v = *(const float4*)&Q[base + (size_t)(qb * 128 + r) * DKK + c4];
        v.x *= QSCALE; v.y *= QSCALE; v.z *= QSCALE; v.w *= QSCALE;
        *(float4*)&Qs[r * 64 + c4] = v;
    }

    float acc[8][4];
    float m_i[8], l_i[8];
#pragma unroll
    for (int i = 0; i < 8; i++) {
        m_i[i] = -CUDART_INF_F; l_i[i] = 0.f;
        acc[i][0] = acc[i][1] = acc[i][2] = acc[i][3] = 0.f;
    }

    int qr[8];
#pragma unroll
    for (int i = 0; i < 8; i++) qr[i] = qb * 128 + ty * 8 + i;

    const int kb_end = 2 * qb + 2;
    for (int kb = 0; kb < kb_end; kb++) {
        __syncthreads();
#pragma unroll
        for (int it = 0; it < 4; it++) {
            int f = tid + it * 256;
            int j  = f >> 4;
            int c4 = (f & 15) << 2;
            float4 kv = *(const float4*)&K[base + (size_t)(kb * 64 + j) * DKK + c4];
            Kst[(c4 + 0) * RK + j] = kv.x;
            Kst[(c4 + 1) * RK + j] = kv.y;
            Kst[(c4 + 2) * RK + j] = kv.z;
            Kst[(c4 + 3) * RK + j] = kv.w;
            float4 vv = *(const float4*)&V[base + (size_t)(kb * 64 + j) * DKK + c4];
            *(float4*)&Vs[j * RK + c4] = vv;
        }
        __syncthreads();

        float st[8][4];
#pragma unroll
        for (int i = 0; i < 8; i++)
            st[i][0] = st[i][1] = st[i][2] = st[i][3] = 0.f;

        for (int k4 = 0; k4 < 64; k4 += 4) {
            float4 b0 = *(const float4*)&Kst[(k4 + 0) * RK + tx * 4];
            float4 b1 = *(const float4*)&Kst[(k4 + 1) * RK + tx * 4];
            float4 b2 = *(const float4*)&Kst[(k4 + 2) * RK + tx * 4];
            float4 b3 = *(const float4*)&Kst[(k4 + 3) * RK + tx * 4];
#pragma unroll
            for (int i = 0; i < 8; i++) {
                float4 a = *(const float4*)&Qs[(ty * 8 + i) * 64 + k4];
                st[i][0] += a.x * b0.x + a.y * b1.x + a.z * b2.x + a.w * b3.x;
                st[i][1] += a.x * b0.y + a.y * b1.y + a.z * b2.y + a.w * b3.y;
                st[i][2] += a.x * b0.z + a.y * b1.z + a.z * b2.z + a.w * b3.z;
                st[i][3] += a.x * b0.w + a.y * b1.w + a.z * b2.w + a.w * b3.w;
            }
        }

        if (kb >= 2 * qb) {
#pragma unroll
            for (int i = 0; i < 8; i++) {
#pragma unroll
                for (int j = 0; j < 4; j++) {
                    int kc = kb * 64 + tx * 4 + j;
                    if (kc > qr[i]) st[i][j] = -CUDART_INF_F;
                }
            }
        }

#pragma unroll
        for (int i = 0; i < 8; i++) {
            float mx = fmaxf(fmaxf(st[i][0], st[i][1]), fmaxf(st[i][2], st[i][3]));
#pragma unroll
            for (int off = 1; off < 16; off <<= 1)
                mx = fmaxf(mx, __shfl_xor_sync(0xffffffffu, mx, off));
            float mnew  = fmaxf(m_i[i], mx);
            float alpha = exp2f(m_i[i] - mnew);
            m_i[i] = mnew;
            float p0 = exp2f(st[i][0] - mnew);
            float p1 = exp2f(st[i][1] - mnew);
            float p2 = exp2f(st[i][2] - mnew);
            float p3 = exp2f(st[i][3] - mnew);
            float rs = (p0 + p1) + (p2 + p3);
#pragma unroll
            for (int off = 1; off < 16; off <<= 1)
                rs += __shfl_xor_sync(0xffffffffu, rs, off);
            l_i[i] = l_i[i] * alpha + rs;
            acc[i][0] *= alpha; acc[i][1] *= alpha;
            acc[i][2] *= alpha; acc[i][3] *= alpha;
            int r = ty * 8 + i;
            Ps[(tx * 4 + 0) * RP + r] = p0;
            Ps[(tx * 4 + 1) * RP + r] = p1;
            Ps[(tx * 4 + 2) * RP + r] = p2;
            Ps[(tx * 4 + 3) * RP + r] = p3;
        }
        __syncthreads();

        for (int j = 0; j < 64; j++) {
            float4 bv = *(const float4*)&Vs[j * RK + tx * 4];
            const float* prow = &Ps[j * RP + ty * 8];
#pragma unroll
            for (int i = 0; i < 8; i++) {
                float p = prow[i];
                acc[i][0] += p * bv.x;
                acc[i][1] += p * bv.y;
                acc[i][2] += p * bv.z;
                acc[i][3] += p * bv.w;
            }
        }
    }

    const int b = bh >> 4;
    const int h = bh & 15;
#pragma unroll
    for (int i = 0; i < 8; i++) {
        float inv = 1.0f / l_i[i];
        float4 o;
        o.x = acc[i][0] * inv; o.y = acc[i][1] * inv;
        o.z = acc[i][2] * inv; o.w = acc[i][3] * inv;
        *(float4*)&O[(size_t)(b * SS + qr[i]) * DM + h * DKK + tx * 4] = o;
    }
}

// ---------------------------------------------------------------------------
extern "C" void kernel_launch(void* const* d_in, const int* in_sizes, int n_in,
                              void* d_out, int out_size)
{
    const float* x  = (const float*)d_in[0];
    const float* Wq = (const float*)d_in[1];
    const float* Wk = (const float*)d_in[2];
    const float* Wv = (const float*)d_in[3];
    const float* Wo = (const float*)d_in[4];
    const int*   tp = (const int*)  d_in[5];
    float* out = (float*)d_out;

    float *gQ, *gK, *gV, *gAO, *gRope;
    __nv_bfloat16 *xh, *xl, *wh, *wl, *aoh, *aol;
    cudaGetSymbolAddress((void**)&gQ,    g_Q);
    cudaGetSymbolAddress((void**)&gK,    g_K);
    cudaGetSymbolAddress((void**)&gV,    g_V);
    cudaGetSymbolAddress((void**)&gAO,   g_AO);
    cudaGetSymbolAddress((void**)&gRope, g_rope);
    cudaGetSymbolAddress((void**)&xh,  g_xh);
    cudaGetSymbolAddress((void**)&xl,  g_xl);
    cudaGetSymbolAddress((void**)&wh,  g_wh);
    cudaGetSymbolAddress((void**)&wl,  g_wl);
    cudaGetSymbolAddress((void**)&aoh, g_aoh);
    cudaGetSymbolAddress((void**)&aol, g_aol);

    cudaFuncSetAttribute(gemm_mma, cudaFuncAttributeMaxDynamicSharedMemorySize, GSMEM);
    const int asmem = SMEM_FLOATS * (int)sizeof(float);
    cudaFuncSetAttribute(attn_kernel, cudaFuncAttributeMaxDynamicSharedMemorySize, asmem);

    const int nx4 = MTOT * DM / 4;
    const int nw4 = DM * DM / 4;
    split_kernel<<<nx4 / 256, 256>>>(x, xh, xl, nx4);
    split_kernel<<<nw4 / 256, 256>>>(Wq, wh + 0 * (size_t)DM * DM, wl + 0 * (size_t)DM * DM, nw4);
    split_kernel<<<nw4 / 256, 256>>>(Wk, wh + 1 * (size_t)DM * DM, wl + 1 * (size_t)DM * DM, nw4);
    split_kernel<<<nw4 / 256, 256>>>(Wv, wh + 2 * (size_t)DM * DM, wl + 2 * (size_t)DM * DM, nw4);
    split_kernel<<<nw4 / 256, 256>>>(Wo, wh + 3 * (size_t)DM * DM, wl + 3 * (size_t)DM * DM, nw4);
    rope_init_kernel<<<SS * 32 / 256, 256>>>(tp, gRope);

    dim3 ggrid(MTOT / 128, DM / 128);    // (64, 8)
    gemm_mma<<<ggrid, 256, GSMEM>>>(xh, xl, wh + 0 * (size_t)DM * DM, wl + 0 * (size_t)DM * DM, gQ, gRope, 0);
    gemm_mma<<<ggrid, 256, GSMEM>>>(xh, xl, wh + 1 * (size_t)DM * DM, wl + 1 * (size_t)DM * DM, gK, gRope, 1);
    gemm_mma<<<ggrid, 256, GSMEM>>>(xh, xl, wh + 2 * (size_t)DM * DM, wl + 2 * (size_t)DM * DM, gV, gRope, 2);

    dim3 agrid(SS / 128, BB * HH);       // (16, 64)
    attn_kernel<<<agrid, 256, asmem>>>(gQ, gK, gV, gAO);

    split_kernel<<<nx4 / 256, 256>>>(gAO, aoh, aol, nx4);
    gemm_mma<<<ggrid, 256, GSMEM>>>(aoh, aol, wh + 3 * (size_t)DM * DM, wl + 3 * (size_t)DM * DM, out, gRope, 3);
}

// round 4
// speedup vs baseline: 2.4979x; 1.7729x over previous
#include <cuda_runtime.h>
#include <cuda_bf16.h>
#include <math.h>
#include <math_constants.h>
#include <cstdint>

#define BB 4
#define SS 2048
#define DM 1024
#define HH 16
#define DKK 64
#define MTOT (BB*SS)   // 8192

// ---------------- scratch (allocation-free) ----------------
__device__ __nv_bfloat16 g_xh[(size_t)MTOT*DM],  g_xl[(size_t)MTOT*DM];
__device__ __nv_bfloat16 g_aoh[(size_t)MTOT*DM], g_aol[(size_t)MTOT*DM];
__device__ __nv_bfloat16 g_wh[(size_t)4*DM*DM],  g_wl[(size_t)4*DM*DM];
__device__ __nv_bfloat16 g_Qh[(size_t)BB*HH*SS*DKK], g_Ql[(size_t)BB*HH*SS*DKK];
__device__ __nv_bfloat16 g_Kh[(size_t)BB*HH*SS*DKK], g_Kl[(size_t)BB*HH*SS*DKK];
__device__ __nv_bfloat16 g_Vh[(size_t)BB*HH*SS*DKK], g_Vl[(size_t)BB*HH*SS*DKK];
__device__ float g_rope[SS*64];   // [s][0..31]=cos, [s][32..63]=sin

// 1/sqrt(64) * log2(e), folded into Q so scores are in exp2 domain
#define ASCALE 0.1803368801111244f

// ---------------- PTX helpers (baseline ISA only) ----------------
__device__ __forceinline__ uint32_t smem_to_u32(const void* p) {
    uint32_t a;
    asm("{ .reg .u64 t; cvta.to.shared.u64 t, %1; cvt.u32.u64 %0, t; }"
        : "=r"(a) : "l"(p));
    return a;
}
__device__ __forceinline__ void cp16(uint32_t dst, const void* src) {
    asm volatile("cp.async.cg.shared.global [%0], [%1], 16;"
                 :: "r"(dst), "l"(src) : "memory");
}
#define CP_COMMIT() asm volatile("cp.async.commit_group;" ::: "memory")
#define CP_WAIT1()  asm volatile("cp.async.wait_group 1;"  ::: "memory")
#define CP_WAIT0()  asm volatile("cp.async.wait_group 0;"  ::: "memory")

__device__ __forceinline__ void ldsm4(uint32_t* r, uint32_t addr) {
    asm volatile("ldmatrix.sync.aligned.m8n8.x4.shared.b16 {%0,%1,%2,%3}, [%4];"
                 : "=r"(r[0]), "=r"(r[1]), "=r"(r[2]), "=r"(r[3]) : "r"(addr));
}
__device__ __forceinline__ void ldsm4t(uint32_t* r, uint32_t addr) {
    asm volatile("ldmatrix.sync.aligned.m8n8.x4.trans.shared.b16 {%0,%1,%2,%3}, [%4];"
                 : "=r"(r[0]), "=r"(r[1]), "=r"(r[2]), "=r"(r[3]) : "r"(addr));
}
__device__ __forceinline__ void mma16816(float* d, const uint32_t* a,
                                         uint32_t b0, uint32_t b1) {
    asm volatile("mma.sync.aligned.m16n8k16.row.col.f32.bf16.bf16.f32 "
                 "{%0,%1,%2,%3}, {%4,%5,%6,%7}, {%8,%9}, {%0,%1,%2,%3};"
                 : "+f"(d[0]), "+f"(d[1]), "+f"(d[2]), "+f"(d[3])
                 : "r"(a[0]), "r"(a[1]), "r"(a[2]), "r"(a[3]), "r"(b0), "r"(b1));
}
__device__ __forceinline__ float ex2(float x) {
    float y;
    asm("ex2.approx.f32 %0, %1;" : "=f"(y) : "f"(x));
    return y;
}
__device__ __forceinline__ uint32_t packbf(float lo, float hi) {
    uint32_t r;
    asm("cvt.rn.bf16x2.f32 %0, %1, %2;" : "=r"(r) : "f"(hi), "f"(lo));
    return r;
}
__device__ __forceinline__ void split2(float d0, float d1, uint32_t& uh, uint32_t& ul) {
    uh = packbf(d0, d1);
    float h0 = __uint_as_float(uh << 16);
    float h1 = __uint_as_float(uh & 0xffff0000u);
    ul = packbf(d0 - h0, d1 - h1);
}

// ---------------------------------------------------------------------------
// fp32 -> (bf16 hi, bf16 lo) split (x and weights)
// ---------------------------------------------------------------------------
__global__ void split_kernel(const float* __restrict__ src,
                             __nv_bfloat16* __restrict__ hi,
                             __nv_bfloat16* __restrict__ lo, int n4)
{
    int i = blockIdx.x * blockDim.x + threadIdx.x;
    if (i >= n4) return;
    float4 v = ((const float4*)src)[i];
    uint32_t h0, l0, h1, l1;
    split2(v.x, v.y, h0, l0);
    split2(v.z, v.w, h1, l1);
    uint2 uh = make_uint2(h0, h1), ul = make_uint2(l0, l1);
    ((uint2*)hi)[i] = uh;
    ((uint2*)lo)[i] = ul;
}

// ---------------------------------------------------------------------------
// RoPE cos/sin table
// ---------------------------------------------------------------------------
__global__ void rope_init_kernel(const int* __restrict__ tokpos, float* __restrict__ rope)
{
    int idx = blockIdx.x * blockDim.x + threadIdx.x;   // 0..65535
    int s = idx >> 5, p = idx & 31;
    float fr = (float)exp2(-(double)p * (13.287712379549449 / 32.0));
    float ang = (float)tokpos[s] * fr;
    float sn, cs;
    sincosf(ang, &sn, &cs);
    rope[s * 64 + p] = cs;
    rope[s * 64 + 32 + p] = sn;
}

// ---------------------------------------------------------------------------
// bf16x3 mma.sync GEMM: C[m,e] = sum_d A[m,d]*W[e,d]
// mode 0: RoPE*ASCALE -> (Qh,Ql)[b,h,s,dk]; mode 1: RoPE -> (Kh,Kl);
// mode 2: -> (Vh,Vl); mode 3: plain fp32 -> out.
// ---------------------------------------------------------------------------
#define GP      40
#define TILE_B  (128*GP*2)         // 10240
#define STAGE_B (4*TILE_B)         // 40960
#define GSMEM   (2*STAGE_B)        // 81920

__device__ __forceinline__ void issue_stage(uint32_t sdst,
    const __nv_bfloat16* __restrict__ Ah, const __nv_bfloat16* __restrict__ Al,
    const __nv_bfloat16* __restrict__ Bh, const __nv_bfloat16* __restrict__ Bl,
    int m0, int n0, int kc, int tid)
{
    const int colb = kc * 64;
#pragma unroll
    for (int it = 0; it < 2; it++) {
        int idx = tid + it * 256;
        int row = idx >> 2;
        int ch  = (idx & 3) * 16;
        uint32_t soff = row * 80 + ch;
        const char* pa = (const char*)(Ah + (size_t)(m0 + row) * DM) + colb + ch;
        const char* pl = (const char*)(Al + (size_t)(m0 + row) * DM) + colb + ch;
        const char* pb = (const char*)(Bh + (size_t)(n0 + row) * DM) + colb + ch;
        const char* pc = (const char*)(Bl + (size_t)(n0 + row) * DM) + colb + ch;
        cp16(sdst + 0 * TILE_B + soff, pa);
        cp16(sdst + 1 * TILE_B + soff, pl);
        cp16(sdst + 2 * TILE_B + soff, pb);
        cp16(sdst + 3 * TILE_B + soff, pc);
    }
}

__global__ __launch_bounds__(256, 1)
void gemm_mma(const __nv_bfloat16* __restrict__ Ah, const __nv_bfloat16* __restrict__ Al,
              const __nv_bfloat16* __restrict__ Bh, const __nv_bfloat16* __restrict__ Bl,
              float* __restrict__ out,
              __nv_bfloat16* __restrict__ oh, __nv_bfloat16* __restrict__ ol,
              const float* __restrict__ rope, int mode)
{
    extern __shared__ char smc[];
    const uint32_t sbase = smem_to_u32(smc);

    const int tid  = threadIdx.x;
    const int wid  = tid >> 5;
    const int lane = tid & 31;
    const int m0 = blockIdx.x * 128;
    const int n0 = blockIdx.y * 128;
    const int wm = (wid & 3) * 32;
    const int wn = (wid >> 2) * 64;

    float acc[2][8][4];
#pragma unroll
    for (int i = 0; i < 2; i++)
#pragma unroll
        for (int j = 0; j < 8; j++)
#pragma unroll
            for (int q = 0; q < 4; q++) acc[i][j][q] = 0.f;

    const uint32_t lrow = (lane & 7) + ((lane >> 3) & 1) * 8;
    const uint32_t kbl  = ((lane >> 4) & 1) * 16;

    issue_stage(sbase, Ah, Al, Bh, Bl, m0, n0, 0, tid);
    CP_COMMIT();

    const int NKC = DM / 32;
    for (int kc = 0; kc < NKC; kc++) {
        if (kc + 1 < NKC) {
            issue_stage(sbase + ((kc + 1) & 1) * STAGE_B, Ah, Al, Bh, Bl,
                        m0, n0, kc + 1, tid);
            CP_COMMIT();
            CP_WAIT1();
        } else {
            CP_WAIT0();
        }
        __syncthreads();

        const uint32_t sb = sbase + (kc & 1) * STAGE_B;
#pragma unroll
        for (int ks = 0; ks < 2; ks++) {
            const uint32_t kb = ks * 32 + kbl;
            uint32_t ah0[4], ah1[4], al0[4], al1[4];
            const uint32_t aadr = sb + (wm + lrow) * 80 + kb;
            ldsm4(ah0, aadr);
            ldsm4(ah1, aadr + 16 * 80);
            ldsm4(al0, aadr + TILE_B);
            ldsm4(al1, aadr + TILE_B + 16 * 80);
            uint32_t bh[4][4], bl[4][4];
#pragma unroll
            for (int nb = 0; nb < 4; nb++) {
                const uint32_t badr = sb + 2 * TILE_B + (wn + nb * 16 + lrow) * 80 + kb;
                ldsm4(bh[nb], badr);
                ldsm4(bl[nb], badr + TILE_B);
            }
#pragma unroll
            for (int nj = 0; nj < 8; nj++) {
                const int nb = nj >> 1, sel = nj & 1;
                const uint32_t b0h = bh[nb][sel], b1h = bh[nb][sel + 2];
                const uint32_t b0l = bl[nb][sel], b1l = bl[nb][sel + 2];
                mma16816(acc[0][nj], ah0, b0h, b1h);
                mma16816(acc[1][nj], ah1, b0h, b1h);
                mma16816(acc[0][nj], ah0, b0l, b1l);
                mma16816(acc[1][nj], ah1, b0l, b1l);
                mma16816(acc[0][nj], al0, b0h, b1h);
                mma16816(acc[1][nj], al1, b0h, b1h);
            }
        }
        __syncthreads();
    }

    // ---- epilogue ----
    const int g = lane >> 2;
    const int t2 = (lane & 3) * 2;
#pragma unroll
    for (int mi = 0; mi < 2; mi++) {
#pragma unroll
        for (int half = 0; half < 2; half++) {
            const int r = m0 + wm + mi * 16 + half * 8 + g;
            const int b = r >> 11;
            const int s = r & 2047;
#pragma unroll
            for (int nj = 0; nj < 8; nj++) {
                const int e = n0 + wn + nj * 8 + t2;
                float d0 = acc[mi][nj][half * 2 + 0];
                float d1 = acc[mi][nj][half * 2 + 1];
                if (mode == 3) {
                    *(float2*)&out[(size_t)r * DM + e] = make_float2(d0, d1);
                } else {
                    const int h  = e >> 6;
                    const int dk = e & 63;
                    if (mode <= 1) {
                        const int p = dk >> 1;
                        float cs = __ldg(&rope[s * 64 + p]);
                        float sn = __ldg(&rope[s * 64 + 32 + p]);
                        float r0 = d0 * cs - d1 * sn;
                        float r1 = d0 * sn + d1 * cs;
                        d0 = r0; d1 = r1;
                        if (mode == 0) { d0 *= ASCALE; d1 *= ASCALE; }
                    }
                    size_t idx = ((size_t)(b * HH + h) * SS + s) * DKK + dk;
                    uint32_t uh, ul;
                    split2(d0, d1, uh, ul);
                    *(uint32_t*)&oh[idx] = uh;
                    *(uint32_t*)&ol[idx] = ul;
                }
            }
        }
    }
}

// ---------------------------------------------------------------------------
// Tensor-core flash attention (bf16x3, causal).
// CTA = 128 q rows of one (b,h); 8 warps x m16. KV tiles of 64 keys,
// double-buffered cp.async. Pitch 144B => conflict-free ldmatrix.
// ---------------------------------------------------------------------------
#define AP      144
#define QT_B    (128*AP)      // 18432
#define KT_B    (64*AP)       // 9216
#define ASTG_B  (4*KT_B)      // 36864
#define ASMEM   (2*QT_B + 2*ASTG_B)   // 110592

__device__ __forceinline__ void issue_kv(uint32_t dst,
    const __nv_bfloat16* __restrict__ Kh, const __nv_bfloat16* __restrict__ Kl,
    const __nv_bfloat16* __restrict__ Vh, const __nv_bfloat16* __restrict__ Vl,
    size_t base, int kb, int tid)
{
#pragma unroll
    for (int it = 0; it < 8; it++) {
        int f   = tid + it * 256;       // 0..2047
        int ten = f >> 9;               // 0..3
        int row = (f >> 3) & 63;
        int ch  = f & 7;
        const __nv_bfloat16* sp = (ten == 0) ? Kh : (ten == 1) ? Kl
                                 : (ten == 2) ? Vh : Vl;
        sp += base + (size_t)(kb * 64 + row) * DKK + ch * 8;
        cp16(dst + ten * KT_B + row * AP + ch * 16, sp);
    }
}

__global__ __launch_bounds__(256, 1)
void attn_mma(const __nv_bfloat16* __restrict__ Qh, const __nv_bfloat16* __restrict__ Ql,
              const __nv_bfloat16* __restrict__ Kh, const __nv_bfloat16* __restrict__ Kl,
              const __nv_bfloat16* __restrict__ Vh, const __nv_bfloat16* __restrict__ Vl,
              __nv_bfloat16* __restrict__ AOh, __nv_bfloat16* __restrict__ AOl)
{
    extern __shared__ char smc[];
    const uint32_t sb = smem_to_u32(smc);
    const uint32_t sQ  = sb;
    const uint32_t sKV = sb + 2 * QT_B;

    const int tid  = threadIdx.x;
    const int wid  = tid >> 5;
    const int lane = tid & 31;
    const int g = lane >> 2;
    const int t = lane & 3;

    const int qb = 15 - (blockIdx.x >> 6);    // heavy q-blocks first
    const int bh = blockIdx.x & 63;
    const size_t base = (size_t)bh * SS * DKK;

    const float NINF = __int_as_float(0xff800000);

    // issue Q (hi+lo) and KV stage 0
#pragma unroll
    for (int it = 0; it < 8; it++) {
        int f   = tid + it * 256;       // 0..2047
        int ten = f >> 10;              // 0..1
        int row = (f >> 3) & 127;
        int ch  = f & 7;
        const __nv_bfloat16* sp = (ten ? Ql : Qh)
            + base + (size_t)(qb * 128 + row) * DKK + ch * 8;
        cp16(sQ + ten * QT_B + row * AP + ch * 16, sp);
    }
    issue_kv(sKV, Kh, Kl, Vh, Vl, base, 0, tid);
    CP_COMMIT();
    CP_WAIT0();
    __syncthreads();

    // Q fragments (persist across all KV blocks)
    const uint32_t lrow = (lane & 7) + ((lane >> 3) & 1) * 8;
    const uint32_t kb16 = ((lane >> 4) & 1) * 16;
    uint32_t qfh[4][4], qfl[4][4];
#pragma unroll
    for (int ks = 0; ks < 4; ks++) {
        uint32_t a = sQ + (wid * 16 + lrow) * AP + ks * 32 + kb16;
        ldsm4(qfh[ks], a);
        ldsm4(qfl[ks], a + QT_B);
    }

    float oacc[8][4];
#pragma unroll
    for (int nj = 0; nj < 8; nj++)
#pragma unroll
        for (int q = 0; q < 4; q++) oacc[nj][q] = 0.f;
    float m0 = NINF, m1 = NINF, l0 = 0.f, l1 = 0.f;

    const int r0 = qb * 128 + wid * 16 + g;
    const int r1 = r0 + 8;

    const uint32_t vrow = (lane & 7) + ((lane >> 4) & 1) * 8;
    const uint32_t vb16 = ((lane >> 3) & 1) * 16;

    const int nkb = 2 * qb + 2;
    for (int kb = 0; kb < nkb; kb++) {
        if (kb + 1 < nkb) {
            issue_kv(sKV + ((kb + 1) & 1) * ASTG_B, Kh, Kl, Vh, Vl, base, kb + 1, tid);
            CP_COMMIT();
            CP_WAIT1();
        } else {
            CP_WAIT0();
        }
        __syncthreads();

        const uint32_t sK = sKV + (kb & 1) * ASTG_B;
        const uint32_t sV = sK + 2 * KT_B;

        // ---- S = Qh*Kh + Qh*Kl + Ql*Kh ----
        float sf[8][4];
#pragma unroll
        for (int nj = 0; nj < 8; nj++)
#pragma unroll
            for (int q = 0; q < 4; q++) sf[nj][q] = 0.f;

#pragma unroll
        for (int ks = 0; ks < 4; ks++) {
            uint32_t kfh[4][4], kfl[4][4];
#pragma unroll
            for (int nt = 0; nt < 4; nt++) {
                uint32_t ba = sK + (nt * 16 + lrow) * AP + ks * 32 + kb16;
                ldsm4(kfh[nt], ba);
                ldsm4(kfl[nt], ba + KT_B);
            }
#pragma unroll
            for (int nj = 0; nj < 8; nj++) {
                const int nt = nj >> 1, sel = nj & 1;
                mma16816(sf[nj], qfh[ks], kfh[nt][sel], kfh[nt][sel + 2]);
                mma16816(sf[nj], qfh[ks], kfl[nt][sel], kfl[nt][sel + 2]);
                mma16816(sf[nj], qfl[ks], kfh[nt][sel], kfh[nt][sel + 2]);
            }
        }

        // ---- causal mask (only near-diagonal blocks) ----
        if (kb >= 2 * qb) {
#pragma unroll
            for (int nj = 0; nj < 8; nj++) {
                int c0 = kb * 64 + nj * 8 + 2 * t;
                if (c0 > r0)     sf[nj][0] = NINF;
                if (c0 + 1 > r0) sf[nj][1] = NINF;
                if (c0 > r1)     sf[nj][2] = NINF;
                if (c0 + 1 > r1) sf[nj][3] = NINF;
            }
        }

        // ---- online softmax (scores already in log2 units) ----
        float mx0 = sf[0][0], mx1 = sf[0][2];
#pragma unroll
        for (int nj = 0; nj < 8; nj++) {
            mx0 = fmaxf(mx0, fmaxf(sf[nj][0], sf[nj][1]));
            mx1 = fmaxf(mx1, fmaxf(sf[nj][2], sf[nj][3]));
        }
        mx0 = fmaxf(mx0, __shfl_xor_sync(0xffffffffu, mx0, 1));
        mx0 = fmaxf(mx0, __shfl_xor_sync(0xffffffffu, mx0, 2));
        mx1 = fmaxf(mx1, __shfl_xor_sync(0xffffffffu, mx1, 1));
        mx1 = fmaxf(mx1, __shfl_xor_sync(0xffffffffu, mx1, 2));
        float mn0 = fmaxf(m0, mx0), mn1 = fmaxf(m1, mx1);
        float al0 = ex2(m0 - mn0), al1 = ex2(m1 - mn1);
        m0 = mn0; m1 = mn1;

        float s0 = 0.f, s1 = 0.f;
#pragma unroll
        for (int nj = 0; nj < 8; nj++) {
            sf[nj][0] = ex2(sf[nj][0] - m0);
            sf[nj][1] = ex2(sf[nj][1] - m0);
            sf[nj][2] = ex2(sf[nj][2] - m1);
            sf[nj][3] = ex2(sf[nj][3] - m1);
            s0 += sf[nj][0] + sf[nj][1];
            s1 += sf[nj][2] + sf[nj][3];
        }
        s0 += __shfl_xor_sync(0xffffffffu, s0, 1);
        s0 += __shfl_xor_sync(0xffffffffu, s0, 2);
        s1 += __shfl_xor_sync(0xffffffffu, s1, 1);
        s1 += __shfl_xor_sync(0xffffffffu, s1, 2);
        l0 = l0 * al0 + s0;
        l1 = l1 * al1 + s1;

#pragma unroll
        for (int nj = 0; nj < 8; nj++) {
            oacc[nj][0] *= al0; oacc[nj][1] *= al0;
            oacc[nj][2] *= al1; oacc[nj][3] *= al1;
        }

        // ---- O += Ph*Vh + Ph*Vl + Pl*Vh ----
#pragma unroll
        for (int ks = 0; ks < 4; ks++) {
            uint32_t vfh[4][4], vfl[4][4];
#pragma unroll
            for (int nt = 0; nt < 4; nt++) {
                uint32_t va = sV + (ks * 16 + vrow) * AP + nt * 32 + vb16;
                ldsm4t(vfh[nt], va);
                ldsm4t(vfl[nt], va + KT_B);
            }
            // P fragments for this k-step from S tiles 2ks, 2ks+1
            uint32_t pah[4], pal[4];
            split2(sf[2 * ks][0],     sf[2 * ks][1],     pah[0], pal[0]);
            split2(sf[2 * ks][2],     sf[2 * ks][3],     pah[1], pal[1]);
            split2(sf[2 * ks + 1][0], sf[2 * ks + 1][1], pah[2], pal[2]);
            split2(sf[2 * ks + 1][2], sf[2 * ks + 1][3], pah[3], pal[3]);
#pragma unroll
            for (int nj = 0; nj < 8; nj++) {
                const int nt = nj >> 1, sel = nj & 1;
                mma16816(oacc[nj], pah, vfh[nt][sel], vfh[nt][sel + 2]);
                mma16816(oacc[nj], pah, vfl[nt][sel], vfl[nt][sel + 2]);
                mma16816(oacc[nj], pal, vfh[nt][sel], vfh[nt][sel + 2]);
            }
        }
        __syncthreads();
    }

    // ---- epilogue: O/l -> bf16 hi/lo at [b*S+s][h*64+dk] ----
    const float inv0 = 1.0f / l0;
    const float inv1 = 1.0f / l1;
    const int b = bh >> 4, h = bh & 15;
    const size_t row0 = (size_t)(b * SS + r0) * DM;
    const size_t row1 = (size_t)(b * SS + r1) * DM;
#pragma unroll
    for (int nj = 0; nj < 8; nj++) {
        const int e = h * 64 + nj * 8 + 2 * t;
        uint32_t uh, ul;
        split2(oacc[nj][0] * inv0, oacc[nj][1] * inv0, uh, ul);
        *(uint32_t*)&AOh[row0 + e] = uh;
        *(uint32_t*)&AOl[row0 + e] = ul;
        split2(oacc[nj][2] * inv1, oacc[nj][3] * inv1, uh, ul);
        *(uint32_t*)&AOh[row1 + e] = uh;
        *(uint32_t*)&AOl[row1 + e] = ul;
    }
}

// ---------------------------------------------------------------------------
extern "C" void kernel_launch(void* const* d_in, const int* in_sizes, int n_in,
                              void* d_out, int out_size)
{
    const float* x  = (const float*)d_in[0];
    const float* Wq = (const float*)d_in[1];
    const float* Wk = (const float*)d_in[2];
    const float* Wv = (const float*)d_in[3];
    const float* Wo = (const float*)d_in[4];
    const int*   tp = (const int*)  d_in[5];
    float* out = (float*)d_out;

    float* gRope;
    __nv_bfloat16 *xh, *xl, *wh, *wl, *aoh, *aol;
    __nv_bfloat16 *qh, *ql, *kh, *kl, *vh, *vl;
    cudaGetSymbolAddress((void**)&gRope, g_rope);
    cudaGetSymbolAddress((void**)&xh,  g_xh);
    cudaGetSymbolAddress((void**)&xl,  g_xl);
    cudaGetSymbolAddress((void**)&wh,  g_wh);
    cudaGetSymbolAddress((void**)&wl,  g_wl);
    cudaGetSymbolAddress((void**)&aoh, g_aoh);
    cudaGetSymbolAddress((void**)&aol, g_aol);
    cudaGetSymbolAddress((void**)&qh,  g_Qh);
    cudaGetSymbolAddress((void**)&ql,  g_Ql);
    cudaGetSymbolAddress((void**)&kh,  g_Kh);
    cudaGetSymbolAddress((void**)&kl,  g_Kl);
    cudaGetSymbolAddress((void**)&vh,  g_Vh);
    cudaGetSymbolAddress((void**)&vl,  g_Vl);

    cudaFuncSetAttribute(gemm_mma, cudaFuncAttributeMaxDynamicSharedMemorySize, GSMEM);
    cudaFuncSetAttribute(attn_mma, cudaFuncAttributeMaxDynamicSharedMemorySize, ASMEM);

    const int nx4 = MTOT * DM / 4;
    const int nw4 = DM * DM / 4;
    split_kernel<<<nx4 / 256, 256>>>(x, xh, xl, nx4);
    split_kernel<<<nw4 / 256, 256>>>(Wq, wh + 0 * (size_t)DM * DM, wl + 0 * (size_t)DM * DM, nw4);
    split_kernel<<<nw4 / 256, 256>>>(Wk, wh + 1 * (size_t)DM * DM, wl + 1 * (size_t)DM * DM, nw4);
    split_kernel<<<nw4 / 256, 256>>>(Wv, wh + 2 * (size_t)DM * DM, wl + 2 * (size_t)DM * DM, nw4);
    split_kernel<<<nw4 / 256, 256>>>(Wo, wh + 3 * (size_t)DM * DM, wl + 3 * (size_t)DM * DM, nw4);
    rope_init_kernel<<<SS * 32 / 256, 256>>>(tp, gRope);

    dim3 ggrid(MTOT / 128, DM / 128);    // (64, 8)
    gemm_mma<<<ggrid, 256, GSMEM>>>(xh, xl, wh + 0 * (size_t)DM * DM, wl + 0 * (size_t)DM * DM,
                                    nullptr, qh, ql, gRope, 0);
    gemm_mma<<<ggrid, 256, GSMEM>>>(xh, xl, wh + 1 * (size_t)DM * DM, wl + 1 * (size_t)DM * DM,
                                    nullptr, kh, kl, gRope, 1);
    gemm_mma<<<ggrid, 256, GSMEM>>>(xh, xl, wh + 2 * (size_t)DM * DM, wl + 2 * (size_t)DM * DM,
                                    nullptr, vh, vl, gRope, 2);

    attn_mma<<<1024, 256, ASMEM>>>(qh, ql, kh, kl, vh, vl, aoh, aol);

    gemm_mma<<<ggrid, 256, GSMEM>>>(aoh, aol, wh + 3 * (size_t)DM * DM, wl + 3 * (size_t)DM * DM,
                                    out, nullptr, nullptr, gRope, 3);
}

// round 5
// speedup vs baseline: 2.6481x; 1.0601x over previous
#include <cuda_runtime.h>
#include <cuda_bf16.h>
#include <math.h>
#include <math_constants.h>
#include <cstdint>

#define BB 4
#define SS 2048
#define DM 1024
#define HH 16
#define DKK 64
#define MTOT (BB*SS)   // 8192

// ---------------- scratch (allocation-free) ----------------
__device__ __nv_bfloat16 g_xh[(size_t)MTOT*DM],  g_xl[(size_t)MTOT*DM];
__device__ __nv_bfloat16 g_aoh[(size_t)MTOT*DM], g_aol[(size_t)MTOT*DM];
__device__ __nv_bfloat16 g_wh[(size_t)4*DM*DM],  g_wl[(size_t)4*DM*DM];
__device__ __nv_bfloat16 g_Qh[(size_t)BB*HH*SS*DKK], g_Ql[(size_t)BB*HH*SS*DKK];
__device__ __nv_bfloat16 g_Kh[(size_t)BB*HH*SS*DKK], g_Kl[(size_t)BB*HH*SS*DKK];
__device__ __nv_bfloat16 g_Vh[(size_t)BB*HH*SS*DKK], g_Vl[(size_t)BB*HH*SS*DKK];
__device__ float g_rope[SS*64];   // [s][0..31]=cos, [s][32..63]=sin

// 1/sqrt(64) * log2(e), folded into Q so scores are in exp2 domain
#define ASCALE 0.1803368801111244f

// ---------------- PTX helpers (baseline ISA only) ----------------
__device__ __forceinline__ uint32_t smem_to_u32(const void* p) {
    uint32_t a;
    asm("{ .reg .u64 t; cvta.to.shared.u64 t, %1; cvt.u32.u64 %0, t; }"
        : "=r"(a) : "l"(p));
    return a;
}
__device__ __forceinline__ void cp16(uint32_t dst, const void* src) {
    asm volatile("cp.async.cg.shared.global [%0], [%1], 16;"
                 :: "r"(dst), "l"(src) : "memory");
}
#define CP_COMMIT() asm volatile("cp.async.commit_group;" ::: "memory")
#define CP_WAIT1()  asm volatile("cp.async.wait_group 1;"  ::: "memory")
#define CP_WAIT0()  asm volatile("cp.async.wait_group 0;"  ::: "memory")

__device__ __forceinline__ void ldsm4(uint32_t* r, uint32_t addr) {
    asm volatile("ldmatrix.sync.aligned.m8n8.x4.shared.b16 {%0,%1,%2,%3}, [%4];"
                 : "=r"(r[0]), "=r"(r[1]), "=r"(r[2]), "=r"(r[3]) : "r"(addr));
}
__device__ __forceinline__ void ldsm4t(uint32_t* r, uint32_t addr) {
    asm volatile("ldmatrix.sync.aligned.m8n8.x4.trans.shared.b16 {%0,%1,%2,%3}, [%4];"
                 : "=r"(r[0]), "=r"(r[1]), "=r"(r[2]), "=r"(r[3]) : "r"(addr));
}
__device__ __forceinline__ void mma16816(float* d, const uint32_t* a,
                                         uint32_t b0, uint32_t b1) {
    asm volatile("mma.sync.aligned.m16n8k16.row.col.f32.bf16.bf16.f32 "
                 "{%0,%1,%2,%3}, {%4,%5,%6,%7}, {%8,%9}, {%0,%1,%2,%3};"
                 : "+f"(d[0]), "+f"(d[1]), "+f"(d[2]), "+f"(d[3])
                 : "r"(a[0]), "r"(a[1]), "r"(a[2]), "r"(a[3]), "r"(b0), "r"(b1));
}
__device__ __forceinline__ float ex2(float x) {
    float y;
    asm("ex2.approx.f32 %0, %1;" : "=f"(y) : "f"(x));
    return y;
}
__device__ __forceinline__ uint32_t packbf(float lo, float hi) {
    uint32_t r;
    asm("cvt.rn.bf16x2.f32 %0, %1, %2;" : "=r"(r) : "f"(hi), "f"(lo));
    return r;
}
__device__ __forceinline__ void split2(float d0, float d1, uint32_t& uh, uint32_t& ul) {
    uh = packbf(d0, d1);
    float h0 = __uint_as_float(uh << 16);
    float h1 = __uint_as_float(uh & 0xffff0000u);
    ul = packbf(d0 - h0, d1 - h1);
}

// ---------------------------------------------------------------------------
// fp32 -> (bf16 hi, bf16 lo) split
// ---------------------------------------------------------------------------
__global__ void split_kernel(const float* __restrict__ src,
                             __nv_bfloat16* __restrict__ hi,
                             __nv_bfloat16* __restrict__ lo, int n4)
{
    int i = blockIdx.x * blockDim.x + threadIdx.x;
    if (i >= n4) return;
    float4 v = ((const float4*)src)[i];
    uint32_t h0, l0, h1, l1;
    split2(v.x, v.y, h0, l0);
    split2(v.z, v.w, h1, l1);
    ((uint2*)hi)[i] = make_uint2(h0, h1);
    ((uint2*)lo)[i] = make_uint2(l0, l1);
}

// ---------------------------------------------------------------------------
// RoPE cos/sin table
// ---------------------------------------------------------------------------
__global__ void rope_init_kernel(const int* __restrict__ tokpos, float* __restrict__ rope)
{
    int idx = blockIdx.x * blockDim.x + threadIdx.x;
    int s = idx >> 5, p = idx & 31;
    float fr = (float)exp2(-(double)p * (13.287712379549449 / 32.0));
    float ang = (float)tokpos[s] * fr;
    float sn, cs;
    sincosf(ang, &sn, &cs);
    rope[s * 64 + p] = cs;
    rope[s * 64 + 32 + p] = sn;
}

// ---------------------------------------------------------------------------
// bf16x3 mma.sync GEMM, 3-stage cp.async pipeline.
// Fused launch: grid (64, 24): wsel = by>>3 (Q/K/V), n0 = (by&7)*128.
// Wo launch (wo=1): grid (64, 8): wsel = 3.
// ---------------------------------------------------------------------------
#define GP      40
#define TILE_B  (128*GP*2)         // 10240
#define STAGE_B (4*TILE_B)         // 40960
#define GSMEM   (3*STAGE_B)        // 122880

__device__ __forceinline__ void issue_stage(uint32_t sdst,
    const __nv_bfloat16* __restrict__ Ah, const __nv_bfloat16* __restrict__ Al,
    const __nv_bfloat16* __restrict__ Bh, const __nv_bfloat16* __restrict__ Bl,
    int m0, int n0, int kc, int tid)
{
    const int colb = kc * 64;
#pragma unroll
    for (int it = 0; it < 2; it++) {
        int idx = tid + it * 256;
        int row = idx >> 2;
        int ch  = (idx & 3) * 16;
        uint32_t soff = row * 80 + ch;
        const char* pa = (const char*)(Ah + (size_t)(m0 + row) * DM) + colb + ch;
        const char* pl = (const char*)(Al + (size_t)(m0 + row) * DM) + colb + ch;
        const char* pb = (const char*)(Bh + (size_t)(n0 + row) * DM) + colb + ch;
        const char* pc = (const char*)(Bl + (size_t)(n0 + row) * DM) + colb + ch;
        cp16(sdst + 0 * TILE_B + soff, pa);
        cp16(sdst + 1 * TILE_B + soff, pl);
        cp16(sdst + 2 * TILE_B + soff, pb);
        cp16(sdst + 3 * TILE_B + soff, pc);
    }
}

__global__ __launch_bounds__(256, 1)
void gemm_mma(const __nv_bfloat16* __restrict__ Ah, const __nv_bfloat16* __restrict__ Al,
              const __nv_bfloat16* __restrict__ WhBase, const __nv_bfloat16* __restrict__ WlBase,
              float* __restrict__ out,
              __nv_bfloat16* __restrict__ qh, __nv_bfloat16* __restrict__ ql,
              __nv_bfloat16* __restrict__ kh, __nv_bfloat16* __restrict__ kl,
              __nv_bfloat16* __restrict__ vvh, __nv_bfloat16* __restrict__ vvl,
              const float* __restrict__ rope, int wo)
{
    extern __shared__ char smc[];
    const uint32_t sbase = smem_to_u32(smc);

    const int tid  = threadIdx.x;
    const int wid  = tid >> 5;
    const int lane = tid & 31;
    const int m0 = blockIdx.x * 128;
    const int by = blockIdx.y;
    const int wsel = wo ? 3 : (by >> 3);
    const int n0 = wo ? by * 128 : (by & 7) * 128;
    const __nv_bfloat16* Bh = WhBase + (size_t)wsel * DM * DM;
    const __nv_bfloat16* Bl = WlBase + (size_t)wsel * DM * DM;

    const int wm = (wid & 3) * 32;
    const int wn = (wid >> 2) * 64;

    float acc[2][8][4];
#pragma unroll
    for (int i = 0; i < 2; i++)
#pragma unroll
        for (int j = 0; j < 8; j++)
#pragma unroll
            for (int q = 0; q < 4; q++) acc[i][j][q] = 0.f;

    const uint32_t lrow = (lane & 7) + ((lane >> 3) & 1) * 8;
    const uint32_t kbl  = ((lane >> 4) & 1) * 16;

    issue_stage(sbase + 0 * STAGE_B, Ah, Al, Bh, Bl, m0, n0, 0, tid);
    CP_COMMIT();
    issue_stage(sbase + 1 * STAGE_B, Ah, Al, Bh, Bl, m0, n0, 1, tid);
    CP_COMMIT();

    const int NKC = DM / 32;   // 32
    for (int kc = 0; kc < NKC; kc++) {
        if (kc + 1 < NKC) CP_WAIT1(); else CP_WAIT0();
        __syncthreads();
        if (kc + 2 < NKC) {
            issue_stage(sbase + ((kc + 2) % 3) * STAGE_B, Ah, Al, Bh, Bl,
                        m0, n0, kc + 2, tid);
            CP_COMMIT();
        }

        const uint32_t sb = sbase + (kc % 3) * STAGE_B;
#pragma unroll
        for (int ks = 0; ks < 2; ks++) {
            const uint32_t kb = ks * 32 + kbl;
            uint32_t ah0[4], ah1[4], al0[4], al1[4];
            const uint32_t aadr = sb + (wm + lrow) * 80 + kb;
            ldsm4(ah0, aadr);
            ldsm4(ah1, aadr + 16 * 80);
            ldsm4(al0, aadr + TILE_B);
            ldsm4(al1, aadr + TILE_B + 16 * 80);
            uint32_t bh[4][4], bl[4][4];
#pragma unroll
            for (int nb = 0; nb < 4; nb++) {
                const uint32_t badr = sb + 2 * TILE_B + (wn + nb * 16 + lrow) * 80 + kb;
                ldsm4(bh[nb], badr);
                ldsm4(bl[nb], badr + TILE_B);
            }
#pragma unroll
            for (int nj = 0; nj < 8; nj++) {
                const int nb = nj >> 1, sel = nj & 1;
                const uint32_t b0h = bh[nb][sel], b1h = bh[nb][sel + 2];
                const uint32_t b0l = bl[nb][sel], b1l = bl[nb][sel + 2];
                mma16816(acc[0][nj], ah0, b0h, b1h);
                mma16816(acc[1][nj], ah1, b0h, b1h);
                mma16816(acc[0][nj], ah0, b0l, b1l);
                mma16816(acc[1][nj], ah1, b0l, b1l);
                mma16816(acc[0][nj], al0, b0h, b1h);
                mma16816(acc[1][nj], al1, b0h, b1h);
            }
        }
    }

    // ---- epilogue ----
    __nv_bfloat16 *oh = qh, *ol = ql;
    if (wsel == 1) { oh = kh; ol = kl; }
    else if (wsel == 2) { oh = vvh; ol = vvl; }

    const int g = lane >> 2;
    const int t2 = (lane & 3) * 2;
#pragma unroll
    for (int mi = 0; mi < 2; mi++) {
#pragma unroll
        for (int half = 0; half < 2; half++) {
            const int r = m0 + wm + mi * 16 + half * 8 + g;
            const int b = r >> 11;
            const int s = r & 2047;
#pragma unroll
            for (int nj = 0; nj < 8; nj++) {
                const int e = n0 + wn + nj * 8 + t2;
                float d0 = acc[mi][nj][half * 2 + 0];
                float d1 = acc[mi][nj][half * 2 + 1];
                if (wsel == 3) {
                    *(float2*)&out[(size_t)r * DM + e] = make_float2(d0, d1);
                } else {
                    const int h  = e >> 6;
                    const int dk = e & 63;
                    if (wsel <= 1) {
                        const int p = dk >> 1;
                        float cs = __ldg(&rope[s * 64 + p]);
                        float sn = __ldg(&rope[s * 64 + 32 + p]);
                        float r0 = d0 * cs - d1 * sn;
                        float r1 = d0 * sn + d1 * cs;
                        d0 = r0; d1 = r1;
                        if (wsel == 0) { d0 *= ASCALE; d1 *= ASCALE; }
                    }
                    size_t idx = ((size_t)(b * HH + h) * SS + s) * DKK + dk;
                    uint32_t uh, ul;
                    split2(d0, d1, uh, ul);
                    *(uint32_t*)&oh[idx] = uh;
                    *(uint32_t*)&ol[idx] = ul;
                }
            }
        }
    }
}

// ---------------------------------------------------------------------------
// Tensor-core flash attention (bf16x3, causal), 3-stage KV pipeline.
// ---------------------------------------------------------------------------
#define AP      144
#define QT_B    (128*AP)      // 18432
#define KT_B    (64*AP)       // 9216
#define ASTG_B  (4*KT_B)      // 36864
#define ASMEM   (2*QT_B + 3*ASTG_B)   // 147456

__device__ __forceinline__ void issue_kv(uint32_t dst,
    const __nv_bfloat16* __restrict__ Kh, const __nv_bfloat16* __restrict__ Kl,
    const __nv_bfloat16* __restrict__ Vh, const __nv_bfloat16* __restrict__ Vl,
    size_t base, int kb, int tid)
{
#pragma unroll
    for (int it = 0; it < 8; it++) {
        int f   = tid + it * 256;
        int ten = f >> 9;
        int row = (f >> 3) & 63;
        int ch  = f & 7;
        const __nv_bfloat16* sp = (ten == 0) ? Kh : (ten == 1) ? Kl
                                 : (ten == 2) ? Vh : Vl;
        sp += base + (size_t)(kb * 64 + row) * DKK + ch * 8;
        cp16(dst + ten * KT_B + row * AP + ch * 16, sp);
    }
}

__global__ __launch_bounds__(256, 1)
void attn_mma(const __nv_bfloat16* __restrict__ Qh, const __nv_bfloat16* __restrict__ Ql,
              const __nv_bfloat16* __restrict__ Kh, const __nv_bfloat16* __restrict__ Kl,
              const __nv_bfloat16* __restrict__ Vh, const __nv_bfloat16* __restrict__ Vl,
              __nv_bfloat16* __restrict__ AOh, __nv_bfloat16* __restrict__ AOl)
{
    extern __shared__ char smc[];
    const uint32_t sb = smem_to_u32(smc);
    const uint32_t sQ  = sb;
    const uint32_t sKV = sb + 2 * QT_B;

    const int tid  = threadIdx.x;
    const int wid  = tid >> 5;
    const int lane = tid & 31;
    const int g = lane >> 2;
    const int t = lane & 3;

    const int qb = 15 - (blockIdx.x >> 6);    // heavy q-blocks first
    const int bh = blockIdx.x & 63;
    const size_t base = (size_t)bh * SS * DKK;
    const int nkb = 2 * qb + 2;               // >= 2

    const float NINF = __int_as_float(0xff800000);

    // group A: Q (hi+lo) + KV0
#pragma unroll
    for (int it = 0; it < 8; it++) {
        int f   = tid + it * 256;
        int ten = f >> 10;
        int row = (f >> 3) & 127;
        int ch  = f & 7;
        const __nv_bfloat16* sp = (ten ? Ql : Qh)
            + base + (size_t)(qb * 128 + row) * DKK + ch * 8;
        cp16(sQ + ten * QT_B + row * AP + ch * 16, sp);
    }
    issue_kv(sKV, Kh, Kl, Vh, Vl, base, 0, tid);
    CP_COMMIT();
    // group B: KV1 (nkb >= 2 always)
    issue_kv(sKV + ASTG_B, Kh, Kl, Vh, Vl, base, 1, tid);
    CP_COMMIT();

    // wait for A (Q + KV0), keep B in flight
    CP_WAIT1();
    __syncthreads();

    const uint32_t lrow = (lane & 7) + ((lane >> 3) & 1) * 8;
    const uint32_t kb16 = ((lane >> 4) & 1) * 16;
    uint32_t qfh[4][4], qfl[4][4];
#pragma unroll
    for (int ks = 0; ks < 4; ks++) {
        uint32_t a = sQ + (wid * 16 + lrow) * AP + ks * 32 + kb16;
        ldsm4(qfh[ks], a);
        ldsm4(qfl[ks], a + QT_B);
    }

    float oacc[8][4];
#pragma unroll
    for (int nj = 0; nj < 8; nj++)
#pragma unroll
        for (int q = 0; q < 4; q++) oacc[nj][q] = 0.f;
    float m0 = NINF, m1 = NINF, l0 = 0.f, l1 = 0.f;

    const int r0 = qb * 128 + wid * 16 + g;
    const int r1 = r0 + 8;

    const uint32_t vrow = (lane & 7) + ((lane >> 4) & 1) * 8;
    const uint32_t vb16 = ((lane >> 3) & 1) * 16;

    for (int kb = 0; kb < nkb; kb++) {
        if (kb + 1 < nkb) CP_WAIT1(); else CP_WAIT0();
        __syncthreads();
        if (kb + 2 < nkb) {
            issue_kv(sKV + ((kb + 2) % 3) * ASTG_B, Kh, Kl, Vh, Vl, base, kb + 2, tid);
            CP_COMMIT();
        }

        const uint32_t sK = sKV + (kb % 3) * ASTG_B;
        const uint32_t sV = sK + 2 * KT_B;

        // ---- S = Qh*Kh + Qh*Kl + Ql*Kh ----
        float sf[8][4];
#pragma unroll
        for (int nj = 0; nj < 8; nj++)
#pragma unroll
            for (int q = 0; q < 4; q++) sf[nj][q] = 0.f;

#pragma unroll
        for (int ks = 0; ks < 4; ks++) {
            uint32_t kfh[4][4], kfl[4][4];
#pragma unroll
            for (int nt = 0; nt < 4; nt++) {
                uint32_t ba = sK + (nt * 16 + lrow) * AP + ks * 32 + kb16;
                ldsm4(kfh[nt], ba);
                ldsm4(kfl[nt], ba + KT_B);
            }
#pragma unroll
            for (int nj = 0; nj < 8; nj++) {
                const int nt = nj >> 1, sel = nj & 1;
                mma16816(sf[nj], qfh[ks], kfh[nt][sel], kfh[nt][sel + 2]);
                mma16816(sf[nj], qfh[ks], kfl[nt][sel], kfl[nt][sel + 2]);
                mma16816(sf[nj], qfl[ks], kfh[nt][sel], kfh[nt][sel + 2]);
            }
        }

        // ---- causal mask ----
        if (kb >= 2 * qb) {
#pragma unroll
            for (int nj = 0; nj < 8; nj++) {
                int c0 = kb * 64 + nj * 8 + 2 * t;
                if (c0 > r0)     sf[nj][0] = NINF;
                if (c0 + 1 > r0) sf[nj][1] = NINF;
                if (c0 > r1)     sf[nj][2] = NINF;
                if (c0 + 1 > r1) sf[nj][3] = NINF;
            }
        }

        // ---- online softmax (base-2 domain) ----
        float mx0 = sf[0][0], mx1 = sf[0][2];
#pragma unroll
        for (int nj = 0; nj < 8; nj++) {
            mx0 = fmaxf(mx0, fmaxf(sf[nj][0], sf[nj][1]));
            mx1 = fmaxf(mx1, fmaxf(sf[nj][2], sf[nj][3]));
        }
        mx0 = fmaxf(mx0, __shfl_xor_sync(0xffffffffu, mx0, 1));
        mx0 = fmaxf(mx0, __shfl_xor_sync(0xffffffffu, mx0, 2));
        mx1 = fmaxf(mx1, __shfl_xor_sync(0xffffffffu, mx1, 1));
        mx1 = fmaxf(mx1, __shfl_xor_sync(0xffffffffu, mx1, 2));
        float mn0 = fmaxf(m0, mx0), mn1 = fmaxf(m1, mx1);
        float al0 = ex2(m0 - mn0), al1 = ex2(m1 - mn1);
        m0 = mn0; m1 = mn1;

        float s0 = 0.f, s1 = 0.f;
#pragma unroll
        for (int nj = 0; nj < 8; nj++) {
            sf[nj][0] = ex2(sf[nj][0] - m0);
            sf[nj][1] = ex2(sf[nj][1] - m0);
            sf[nj][2] = ex2(sf[nj][2] - m1);
            sf[nj][3] = ex2(sf[nj][3] - m1);
            s0 += sf[nj][0] + sf[nj][1];
            s1 += sf[nj][2] + sf[nj][3];
        }
        s0 += __shfl_xor_sync(0xffffffffu, s0, 1);
        s0 += __shfl_xor_sync(0xffffffffu, s0, 2);
        s1 += __shfl_xor_sync(0xffffffffu, s1, 1);
        s1 += __shfl_xor_sync(0xffffffffu, s1, 2);
        l0 = l0 * al0 + s0;
        l1 = l1 * al1 + s1;

#pragma unroll
        for (int nj = 0; nj < 8; nj++) {
            oacc[nj][0] *= al0; oacc[nj][1] *= al0;
            oacc[nj][2] *= al1; oacc[nj][3] *= al1;
        }

        // ---- O += Ph*Vh + Ph*Vl + Pl*Vh ----
#pragma unroll
        for (int ks = 0; ks < 4; ks++) {
            uint32_t vfh[4][4], vfl[4][4];
#pragma unroll
            for (int nt = 0; nt < 4; nt++) {
                uint32_t va = sV + (ks * 16 + vrow) * AP + nt * 32 + vb16;
                ldsm4t(vfh[nt], va);
                ldsm4t(vfl[nt], va + KT_B);
            }
            uint32_t pah[4], pal[4];
            split2(sf[2 * ks][0],     sf[2 * ks][1],     pah[0], pal[0]);
            split2(sf[2 * ks][2],     sf[2 * ks][3],     pah[1], pal[1]);
            split2(sf[2 * ks + 1][0], sf[2 * ks + 1][1], pah[2], pal[2]);
            split2(sf[2 * ks + 1][2], sf[2 * ks + 1][3], pah[3], pal[3]);
#pragma unroll
            for (int nj = 0; nj < 8; nj++) {
                const int nt = nj >> 1, sel = nj & 1;
                mma16816(oacc[nj], pah, vfh[nt][sel], vfh[nt][sel + 2]);
                mma16816(oacc[nj], pah, vfl[nt][sel], vfl[nt][sel + 2]);
                mma16816(oacc[nj], pal, vfh[nt][sel], vfh[nt][sel + 2]);
            }
        }
    }

    // ---- epilogue: O/l -> bf16 hi/lo at [b*S+s][h*64+dk] ----
    const float inv0 = 1.0f / l0;
    const float inv1 = 1.0f / l1;
    const int b = bh >> 4, h = bh & 15;
    const size_t row0 = (size_t)(b * SS + r0) * DM;
    const size_t row1 = (size_t)(b * SS + r1) * DM;
#pragma unroll
    for (int nj = 0; nj < 8; nj++) {
        const int e = h * 64 + nj * 8 + 2 * t;
        uint32_t uh, ul;
        split2(oacc[nj][0] * inv0, oacc[nj][1] * inv0, uh, ul);
        *(uint32_t*)&AOh[row0 + e] = uh;
        *(uint32_t*)&AOl[row0 + e] = ul;
        split2(oacc[nj][2] * inv1, oacc[nj][3] * inv1, uh, ul);
        *(uint32_t*)&AOh[row1 + e] = uh;
        *(uint32_t*)&AOl[row1 + e] = ul;
    }
}

// ---------------------------------------------------------------------------
extern "C" void kernel_launch(void* const* d_in, const int* in_sizes, int n_in,
                              void* d_out, int out_size)
{
    const float* x  = (const float*)d_in[0];
    const float* Wq = (const float*)d_in[1];
    const float* Wk = (const float*)d_in[2];
    const float* Wv = (const float*)d_in[3];
    const float* Wo = (const float*)d_in[4];
    const int*   tp = (const int*)  d_in[5];
    float* out = (float*)d_out;

    float* gRope;
    __nv_bfloat16 *xh, *xl, *wh, *wl, *aoh, *aol;
    __nv_bfloat16 *qh, *ql, *kh, *kl, *vh, *vl;
    cudaGetSymbolAddress((void**)&gRope, g_rope);
    cudaGetSymbolAddress((void**)&xh,  g_xh);
    cudaGetSymbolAddress((void**)&xl,  g_xl);
    cudaGetSymbolAddress((void**)&wh,  g_wh);
    cudaGetSymbolAddress((void**)&wl,  g_wl);
    cudaGetSymbolAddress((void**)&aoh, g_aoh);
    cudaGetSymbolAddress((void**)&aol, g_aol);
    cudaGetSymbolAddress((void**)&qh,  g_Qh);
    cudaGetSymbolAddress((void**)&ql,  g_Ql);
    cudaGetSymbolAddress((void**)&kh,  g_Kh);
    cudaGetSymbolAddress((void**)&kl,  g_Kl);
    cudaGetSymbolAddress((void**)&vh,  g_Vh);
    cudaGetSymbolAddress((void**)&vl,  g_Vl);

    cudaFuncSetAttribute(gemm_mma, cudaFuncAttributeMaxDynamicSharedMemorySize, GSMEM);
    cudaFuncSetAttribute(attn_mma, cudaFuncAttributeMaxDynamicSharedMemorySize, ASMEM);

    const int nx4 = MTOT * DM / 4;
    const int nw4 = DM * DM / 4;
    split_kernel<<<nx4 / 256, 256>>>(x, xh, xl, nx4);
    split_kernel<<<nw4 / 256, 256>>>(Wq, wh + 0 * (size_t)DM * DM, wl + 0 * (size_t)DM * DM, nw4);
    split_kernel<<<nw4 / 256, 256>>>(Wk, wh + 1 * (size_t)DM * DM, wl + 1 * (size_t)DM * DM, nw4);
    split_kernel<<<nw4 / 256, 256>>>(Wv, wh + 2 * (size_t)DM * DM, wl + 2 * (size_t)DM * DM, nw4);
    split_kernel<<<nw4 / 256, 256>>>(Wo, wh + 3 * (size_t)DM * DM, wl + 3 * (size_t)DM * DM, nw4);
    rope_init_kernel<<<SS * 32 / 256, 256>>>(tp, gRope);

    // fused QKV projections: grid (64, 24)
    dim3 qkvgrid(MTOT / 128, 24);
    gemm_mma<<<qkvgrid, 256, GSMEM>>>(xh, xl, wh, wl, nullptr,
                                      qh, ql, kh, kl, vh, vl, gRope, 0);

    attn_mma<<<1024, 256, ASMEM>>>(qh, ql, kh, kl, vh, vl, aoh, aol);

    // Wo projection: grid (64, 8), wsel=3
    dim3 wogrid(MTOT / 128, 8);
    gemm_mma<<<wogrid, 256, GSMEM>>>(aoh, aol, wh, wl, out,
                                     qh, ql, kh, kl, vh, vl, gRope, 1);
}

// round 6
// speedup vs baseline: 2.9132x; 1.1001x over previous
#include <cuda_runtime.h>
#include <cuda_bf16.h>
#include <math.h>
#include <math_constants.h>
#include <cstdint>

#define BB 4
#define SS 2048
#define DM 1024
#define HH 16
#define DKK 64
#define MTOT (BB*SS)   // 8192

// ---------------- scratch (allocation-free) ----------------
__device__ __nv_bfloat16 g_xh[(size_t)MTOT*DM],  g_xl[(size_t)MTOT*DM];
__device__ __nv_bfloat16 g_aoh[(size_t)MTOT*DM], g_aol[(size_t)MTOT*DM];
__device__ __nv_bfloat16 g_wh[(size_t)4*DM*DM],  g_wl[(size_t)4*DM*DM];
__device__ __nv_bfloat16 g_Qh[(size_t)BB*HH*SS*DKK], g_Ql[(size_t)BB*HH*SS*DKK];
__device__ __nv_bfloat16 g_Kh[(size_t)BB*HH*SS*DKK], g_Kl[(size_t)BB*HH*SS*DKK];
__device__ __nv_bfloat16 g_Vh[(size_t)BB*HH*SS*DKK], g_Vl[(size_t)BB*HH*SS*DKK];
__device__ float g_rope[SS*64];   // [s][0..31]=cos, [s][32..63]=sin

#define ASCALE 0.1803368801111244f   // 1/sqrt(64)*log2(e)

// ---------------- PTX helpers ----------------
__device__ __forceinline__ uint32_t smem_to_u32(const void* p) {
    uint32_t a;
    asm("{ .reg .u64 t; cvta.to.shared.u64 t, %1; cvt.u32.u64 %0, t; }"
        : "=r"(a) : "l"(p));
    return a;
}
__device__ __forceinline__ void cp16(uint32_t dst, const void* src) {
    asm volatile("cp.async.cg.shared.global [%0], [%1], 16;"
                 :: "r"(dst), "l"(src) : "memory");
}
#define CP_COMMIT() asm volatile("cp.async.commit_group;" ::: "memory")
#define CP_WAIT1()  asm volatile("cp.async.wait_group 1;"  ::: "memory")
#define CP_WAIT0()  asm volatile("cp.async.wait_group 0;"  ::: "memory")

__device__ __forceinline__ void ldsm4(uint32_t* r, uint32_t addr) {
    asm volatile("ldmatrix.sync.aligned.m8n8.x4.shared.b16 {%0,%1,%2,%3}, [%4];"
                 : "=r"(r[0]), "=r"(r[1]), "=r"(r[2]), "=r"(r[3]) : "r"(addr));
}
__device__ __forceinline__ void ldsm4t(uint32_t* r, uint32_t addr) {
    asm volatile("ldmatrix.sync.aligned.m8n8.x4.trans.shared.b16 {%0,%1,%2,%3}, [%4];"
                 : "=r"(r[0]), "=r"(r[1]), "=r"(r[2]), "=r"(r[3]) : "r"(addr));
}
__device__ __forceinline__ void mma16816(float* d, const uint32_t* a,
                                         uint32_t b0, uint32_t b1) {
    asm volatile("mma.sync.aligned.m16n8k16.row.col.f32.bf16.bf16.f32 "
                 "{%0,%1,%2,%3}, {%4,%5,%6,%7}, {%8,%9}, {%0,%1,%2,%3};"
                 : "+f"(d[0]), "+f"(d[1]), "+f"(d[2]), "+f"(d[3])
                 : "r"(a[0]), "r"(a[1]), "r"(a[2]), "r"(a[3]), "r"(b0), "r"(b1));
}
__device__ __forceinline__ float ex2(float x) {
    float y;
    asm("ex2.approx.f32 %0, %1;" : "=f"(y) : "f"(x));
    return y;
}
__device__ __forceinline__ uint32_t packbf(float lo, float hi) {
    uint32_t r;
    asm("cvt.rn.bf16x2.f32 %0, %1, %2;" : "=r"(r) : "f"(hi), "f"(lo));
    return r;
}
__device__ __forceinline__ void split2(float d0, float d1, uint32_t& uh, uint32_t& ul) {
    uh = packbf(d0, d1);
    float h0 = __uint_as_float(uh << 16);
    float h1 = __uint_as_float(uh & 0xffff0000u);
    ul = packbf(d0 - h0, d1 - h1);
}

// ---------------------------------------------------------------------------
// fp32 -> (bf16 hi, bf16 lo) splits
// ---------------------------------------------------------------------------
__global__ void split_kernel(const float* __restrict__ src,
                             __nv_bfloat16* __restrict__ hi,
                             __nv_bfloat16* __restrict__ lo, int n4)
{
    int i = blockIdx.x * blockDim.x + threadIdx.x;
    if (i >= n4) return;
    float4 v = ((const float4*)src)[i];
    uint32_t h0, l0, h1, l1;
    split2(v.x, v.y, h0, l0);
    split2(v.z, v.w, h1, l1);
    ((uint2*)hi)[i] = make_uint2(h0, h1);
    ((uint2*)lo)[i] = make_uint2(l0, l1);
}

// all 4 weights in one launch; blockIdx.y selects
__global__ void split_w_kernel(const float* __restrict__ w0, const float* __restrict__ w1,
                               const float* __restrict__ w2, const float* __restrict__ w3,
                               __nv_bfloat16* __restrict__ hi,
                               __nv_bfloat16* __restrict__ lo)
{
    const int wsel = blockIdx.y;
    const float* src = (wsel == 0) ? w0 : (wsel == 1) ? w1 : (wsel == 2) ? w2 : w3;
    size_t off = (size_t)wsel * (DM * DM / 4);
    int i = blockIdx.x * blockDim.x + threadIdx.x;
    float4 v = ((const float4*)src)[i];
    uint32_t h0, l0, h1, l1;
    split2(v.x, v.y, h0, l0);
    split2(v.z, v.w, h1, l1);
    ((uint2*)hi)[off + i] = make_uint2(h0, h1);
    ((uint2*)lo)[off + i] = make_uint2(l0, l1);
}

__global__ void rope_init_kernel(const int* __restrict__ tokpos, float* __restrict__ rope)
{
    int idx = blockIdx.x * blockDim.x + threadIdx.x;
    int s = idx >> 5, p = idx & 31;
    float fr = (float)exp2(-(double)p * (13.287712379549449 / 32.0));
    float ang = (float)tokpos[s] * fr;
    float sn, cs;
    sincosf(ang, &sn, &cs);
    rope[s * 64 + p] = cs;
    rope[s * 64 + 32 + p] = sn;
}

// ---------------------------------------------------------------------------
// bf16x3 mma.sync GEMM, 2-stage pipeline, 2 CTAs/SM.
// ---------------------------------------------------------------------------
#define GP      40
#define TILE_B  (128*GP*2)         // 10240
#define STAGE_B (4*TILE_B)         // 40960
#define GSMEM   (2*STAGE_B)        // 81920

__device__ __forceinline__ void issue_stage(uint32_t sdst,
    const __nv_bfloat16* __restrict__ Ah, const __nv_bfloat16* __restrict__ Al,
    const __nv_bfloat16* __restrict__ Bh, const __nv_bfloat16* __restrict__ Bl,
    int m0, int n0, int kc, int tid)
{
    const int colb = kc * 64;
#pragma unroll
    for (int it = 0; it < 2; it++) {
        int idx = tid + it * 256;
        int row = idx >> 2;
        int ch  = (idx & 3) * 16;
        uint32_t soff = row * 80 + ch;
        const char* pa = (const char*)(Ah + (size_t)(m0 + row) * DM) + colb + ch;
        const char* pl = (const char*)(Al + (size_t)(m0 + row) * DM) + colb + ch;
        const char* pb = (const char*)(Bh + (size_t)(n0 + row) * DM) + colb + ch;
        const char* pc = (const char*)(Bl + (size_t)(n0 + row) * DM) + colb + ch;
        cp16(sdst + 0 * TILE_B + soff, pa);
        cp16(sdst + 1 * TILE_B + soff, pl);
        cp16(sdst + 2 * TILE_B + soff, pb);
        cp16(sdst + 3 * TILE_B + soff, pc);
    }
}

__global__ __launch_bounds__(256, 2)
void gemm_mma(const __nv_bfloat16* __restrict__ Ah, const __nv_bfloat16* __restrict__ Al,
              const __nv_bfloat16* __restrict__ WhBase, const __nv_bfloat16* __restrict__ WlBase,
              float* __restrict__ out,
              __nv_bfloat16* __restrict__ qh, __nv_bfloat16* __restrict__ ql,
              __nv_bfloat16* __restrict__ kh, __nv_bfloat16* __restrict__ kl,
              __nv_bfloat16* __restrict__ vvh, __nv_bfloat16* __restrict__ vvl,
              const float* __restrict__ rope, int wo)
{
    extern __shared__ char smc[];
    const uint32_t sbase = smem_to_u32(smc);

    const int tid  = threadIdx.x;
    const int wid  = tid >> 5;
    const int lane = tid & 31;
    const int m0 = blockIdx.x * 128;
    const int by = blockIdx.y;
    const int wsel = wo ? 3 : (by >> 3);
    const int n0 = wo ? by * 128 : (by & 7) * 128;
    const __nv_bfloat16* Bh = WhBase + (size_t)wsel * DM * DM;
    const __nv_bfloat16* Bl = WlBase + (size_t)wsel * DM * DM;

    const int wm = (wid & 3) * 32;
    const int wn = (wid >> 2) * 64;

    float acc[2][8][4];
#pragma unroll
    for (int i = 0; i < 2; i++)
#pragma unroll
        for (int j = 0; j < 8; j++)
#pragma unroll
            for (int q = 0; q < 4; q++) acc[i][j][q] = 0.f;

    const uint32_t lrow = (lane & 7) + ((lane >> 3) & 1) * 8;
    const uint32_t kbl  = ((lane >> 4) & 1) * 16;

    issue_stage(sbase, Ah, Al, Bh, Bl, m0, n0, 0, tid);
    CP_COMMIT();

    const int NKC = DM / 32;   // 32
    for (int kc = 0; kc < NKC; kc++) {
        if (kc + 1 < NKC) {
            issue_stage(sbase + ((kc + 1) & 1) * STAGE_B, Ah, Al, Bh, Bl,
                        m0, n0, kc + 1, tid);
            CP_COMMIT();
            CP_WAIT1();
        } else {
            CP_WAIT0();
        }
        __syncthreads();

        const uint32_t sb = sbase + (kc & 1) * STAGE_B;
#pragma unroll
        for (int ks = 0; ks < 2; ks++) {
            const uint32_t kb = ks * 32 + kbl;
            uint32_t ah0[4], ah1[4], al0[4], al1[4];
            const uint32_t aadr = sb + (wm + lrow) * 80 + kb;
            ldsm4(ah0, aadr);
            ldsm4(ah1, aadr + 16 * 80);
            ldsm4(al0, aadr + TILE_B);
            ldsm4(al1, aadr + TILE_B + 16 * 80);
#pragma unroll
            for (int nb = 0; nb < 4; nb++) {
                uint32_t bh[4], bl[4];   // low liveness: per-nb
                const uint32_t badr = sb + 2 * TILE_B + (wn + nb * 16 + lrow) * 80 + kb;
                ldsm4(bh, badr);
                ldsm4(bl, badr + TILE_B);
#pragma unroll
                for (int sel = 0; sel < 2; sel++) {
                    const int nj = nb * 2 + sel;
                    const uint32_t b0h = bh[sel], b1h = bh[sel + 2];
                    const uint32_t b0l = bl[sel], b1l = bl[sel + 2];
                    mma16816(acc[0][nj], ah0, b0h, b1h);
                    mma16816(acc[1][nj], ah1, b0h, b1h);
                    mma16816(acc[0][nj], ah0, b0l, b1l);
                    mma16816(acc[1][nj], ah1, b0l, b1l);
                    mma16816(acc[0][nj], al0, b0h, b1h);
                    mma16816(acc[1][nj], al1, b0h, b1h);
                }
            }
        }
        __syncthreads();
    }

    // ---- epilogue ----
    __nv_bfloat16 *oh = qh, *ol = ql;
    if (wsel == 1) { oh = kh; ol = kl; }
    else if (wsel == 2) { oh = vvh; ol = vvl; }

    const int g = lane >> 2;
    const int t2 = (lane & 3) * 2;
#pragma unroll
    for (int mi = 0; mi < 2; mi++) {
#pragma unroll
        for (int half = 0; half < 2; half++) {
            const int r = m0 + wm + mi * 16 + half * 8 + g;
            const int b = r >> 11;
            const int s = r & 2047;
#pragma unroll
            for (int nj = 0; nj < 8; nj++) {
                const int e = n0 + wn + nj * 8 + t2;
                float d0 = acc[mi][nj][half * 2 + 0];
                float d1 = acc[mi][nj][half * 2 + 1];
                if (wsel == 3) {
                    *(float2*)&out[(size_t)r * DM + e] = make_float2(d0, d1);
                } else {
                    const int h  = e >> 6;
                    const int dk = e & 63;
                    if (wsel <= 1) {
                        const int p = dk >> 1;
                        float cs = __ldg(&rope[s * 64 + p]);
                        float sn = __ldg(&rope[s * 64 + 32 + p]);
                        float r0 = d0 * cs - d1 * sn;
                        float r1 = d0 * sn + d1 * cs;
                        d0 = r0; d1 = r1;
                        if (wsel == 0) { d0 *= ASCALE; d1 *= ASCALE; }
                    }
                    size_t idx = ((size_t)(b * HH + h) * SS + s) * DKK + dk;
                    uint32_t uh, ul;
                    split2(d0, d1, uh, ul);
                    *(uint32_t*)&oh[idx] = uh;
                    *(uint32_t*)&ol[idx] = ul;
                }
            }
        }
    }
}

// ---------------------------------------------------------------------------
// Tensor-core flash attention (bf16x3, causal), 2-stage KV, 2 CTAs/SM.
// ---------------------------------------------------------------------------
#define AP      144
#define QT_B    (128*AP)      // 18432
#define KT_B    (64*AP)       // 9216
#define ASTG_B  (4*KT_B)      // 36864
#define ASMEM   (2*QT_B + 2*ASTG_B)   // 110592

__device__ __forceinline__ void issue_kv(uint32_t dst,
    const __nv_bfloat16* __restrict__ Kh, const __nv_bfloat16* __restrict__ Kl,
    const __nv_bfloat16* __restrict__ Vh, const __nv_bfloat16* __restrict__ Vl,
    size_t base, int kb, int tid)
{
#pragma unroll
    for (int it = 0; it < 8; it++) {
        int f   = tid + it * 256;
        int ten = f >> 9;
        int row = (f >> 3) & 63;
        int ch  = f & 7;
        const __nv_bfloat16* sp = (ten == 0) ? Kh : (ten == 1) ? Kl
                                 : (ten == 2) ? Vh : Vl;
        sp += base + (size_t)(kb * 64 + row) * DKK + ch * 8;
        cp16(dst + ten * KT_B + row * AP + ch * 16, sp);
    }
}

__global__ __launch_bounds__(256, 2)
void attn_mma(const __nv_bfloat16* __restrict__ Qh, const __nv_bfloat16* __restrict__ Ql,
              const __nv_bfloat16* __restrict__ Kh, const __nv_bfloat16* __restrict__ Kl,
              const __nv_bfloat16* __restrict__ Vh, const __nv_bfloat16* __restrict__ Vl,
              __nv_bfloat16* __restrict__ AOh, __nv_bfloat16* __restrict__ AOl)
{
    extern __shared__ char smc[];
    const uint32_t sb = smem_to_u32(smc);
    const uint32_t sQ  = sb;
    const uint32_t sKV = sb + 2 * QT_B;

    const int tid  = threadIdx.x;
    const int wid  = tid >> 5;
    const int lane = tid & 31;
    const int g = lane >> 2;
    const int t = lane & 3;

    const int qb = 15 - (blockIdx.x >> 6);    // heavy q-blocks first
    const int bh = blockIdx.x & 63;
    const size_t base = (size_t)bh * SS * DKK;
    const int nkb = 2 * qb + 2;               // >= 2

    const float NINF = __int_as_float(0xff800000);

    // group 0: Q (hi+lo) + KV0 ; group 1: KV1
#pragma unroll
    for (int it = 0; it < 8; it++) {
        int f   = tid + it * 256;
        int ten = f >> 10;
        int row = (f >> 3) & 127;
        int ch  = f & 7;
        const __nv_bfloat16* sp = (ten ? Ql : Qh)
            + base + (size_t)(qb * 128 + row) * DKK + ch * 8;
        cp16(sQ + ten * QT_B + row * AP + ch * 16, sp);
    }
    issue_kv(sKV, Kh, Kl, Vh, Vl, base, 0, tid);
    CP_COMMIT();
    issue_kv(sKV + ASTG_B, Kh, Kl, Vh, Vl, base, 1, tid);
    CP_COMMIT();

    CP_WAIT1();            // group 0 (Q + KV0) complete
    __syncthreads();

    const uint32_t lrow = (lane & 7) + ((lane >> 3) & 1) * 8;
    const uint32_t kb16 = ((lane >> 4) & 1) * 16;
    uint32_t qfh[4][4], qfl[4][4];
#pragma unroll
    for (int ks = 0; ks < 4; ks++) {
        uint32_t a = sQ + (wid * 16 + lrow) * AP + ks * 32 + kb16;
        ldsm4(qfh[ks], a);
        ldsm4(qfl[ks], a + QT_B);
    }

    float oacc[8][4];
#pragma unroll
    for (int nj = 0; nj < 8; nj++)
#pragma unroll
        for (int q = 0; q < 4; q++) oacc[nj][q] = 0.f;
    float m0 = NINF, m1 = NINF, l0 = 0.f, l1 = 0.f;

    const int r0 = qb * 128 + wid * 16 + g;
    const int r1 = r0 + 8;

    const uint32_t vrow = (lane & 7) + ((lane >> 4) & 1) * 8;
    const uint32_t vb16 = ((lane >> 3) & 1) * 16;

    for (int kb = 0; kb < nkb; kb++) {
        if (kb + 1 < nkb) CP_WAIT1(); else CP_WAIT0();   // group kb complete
        __syncthreads();

        const uint32_t sK = sKV + (kb & 1) * ASTG_B;
        const uint32_t sV = sK + 2 * KT_B;

        // ---- S = Qh*Kh + Qh*Kl + Ql*Kh ----
        float sf[8][4];
#pragma unroll
        for (int nj = 0; nj < 8; nj++)
#pragma unroll
            for (int q = 0; q < 4; q++) sf[nj][q] = 0.f;

#pragma unroll
        for (int ks = 0; ks < 4; ks++) {
#pragma unroll
            for (int nt = 0; nt < 4; nt++) {
                uint32_t kfh[4], kfl[4];   // low liveness: per-nt
                uint32_t ba = sK + (nt * 16 + lrow) * AP + ks * 32 + kb16;
                ldsm4(kfh, ba);
                ldsm4(kfl, ba + KT_B);
#pragma unroll
                for (int sel = 0; sel < 2; sel++) {
                    const int nj = nt * 2 + sel;
                    mma16816(sf[nj], qfh[ks], kfh[sel], kfh[sel + 2]);
                    mma16816(sf[nj], qfh[ks], kfl[sel], kfl[sel + 2]);
                    mma16816(sf[nj], qfl[ks], kfh[sel], kfh[sel + 2]);
                }
            }
        }

        // ---- causal mask ----
        if (kb >= 2 * qb) {
#pragma unroll
            for (int nj = 0; nj < 8; nj++) {
                int c0 = kb * 64 + nj * 8 + 2 * t;
                if (c0 > r0)     sf[nj][0] = NINF;
                if (c0 + 1 > r0) sf[nj][1] = NINF;
                if (c0 > r1)     sf[nj][2] = NINF;
                if (c0 + 1 > r1) sf[nj][3] = NINF;
            }
        }

        // ---- online softmax (base-2 domain) ----
        float mx0 = sf[0][0], mx1 = sf[0][2];
#pragma unroll
        for (int nj = 0; nj < 8; nj++) {
            mx0 = fmaxf(mx0, fmaxf(sf[nj][0], sf[nj][1]));
            mx1 = fmaxf(mx1, fmaxf(sf[nj][2], sf[nj][3]));
        }
        mx0 = fmaxf(mx0, __shfl_xor_sync(0xffffffffu, mx0, 1));
        mx0 = fmaxf(mx0, __shfl_xor_sync(0xffffffffu, mx0, 2));
        mx1 = fmaxf(mx1, __shfl_xor_sync(0xffffffffu, mx1, 1));
        mx1 = fmaxf(mx1, __shfl_xor_sync(0xffffffffu, mx1, 2));
        float mn0 = fmaxf(m0, mx0), mn1 = fmaxf(m1, mx1);
        float al0 = ex2(m0 - mn0), al1 = ex2(m1 - mn1);
        m0 = mn0; m1 = mn1;

        float s0 = 0.f, s1 = 0.f;
#pragma unroll
        for (int nj = 0; nj < 8; nj++) {
            sf[nj][0] = ex2(sf[nj][0] - m0);
            sf[nj][1] = ex2(sf[nj][1] - m0);
            sf[nj][2] = ex2(sf[nj][2] - m1);
            sf[nj][3] = ex2(sf[nj][3] - m1);
            s0 += sf[nj][0] + sf[nj][1];
            s1 += sf[nj][2] + sf[nj][3];
        }
        s0 += __shfl_xor_sync(0xffffffffu, s0, 1);
        s0 += __shfl_xor_sync(0xffffffffu, s0, 2);
        s1 += __shfl_xor_sync(0xffffffffu, s1, 1);
        s1 += __shfl_xor_sync(0xffffffffu, s1, 2);
        l0 = l0 * al0 + s0;
        l1 = l1 * al1 + s1;

#pragma unroll
        for (int nj = 0; nj < 8; nj++) {
            oacc[nj][0] *= al0; oacc[nj][1] *= al0;
            oacc[nj][2] *= al1; oacc[nj][3] *= al1;
        }

        // ---- O += Ph*Vh + Ph*Vl + Pl*Vh ----
#pragma unroll
        for (int ks = 0; ks < 4; ks++) {
            uint32_t pah[4], pal[4];
            split2(sf[2 * ks][0],     sf[2 * ks][1],     pah[0], pal[0]);
            split2(sf[2 * ks][2],     sf[2 * ks][3],     pah[1], pal[1]);
            split2(sf[2 * ks + 1][0], sf[2 * ks + 1][1], pah[2], pal[2]);
            split2(sf[2 * ks + 1][2], sf[2 * ks + 1][3], pah[3], pal[3]);
#pragma unroll
            for (int nt = 0; nt < 4; nt++) {
                uint32_t vfh[4], vfl[4];   // low liveness: per-nt
                uint32_t va = sV + (ks * 16 + vrow) * AP + nt * 32 + vb16;
                ldsm4t(vfh, va);
                ldsm4t(vfl, va + KT_B);
#pragma unroll
                for (int sel = 0; sel < 2; sel++) {
                    const int nj = nt * 2 + sel;
                    mma16816(oacc[nj], pah, vfh[sel], vfh[sel + 2]);
                    mma16816(oacc[nj], pah, vfl[sel], vfl[sel + 2]);
                    mma16816(oacc[nj], pal, vfh[sel], vfh[sel + 2]);
                }
            }
        }
        __syncthreads();   // all warps done with buffer (kb&1) before refill

        if (kb + 2 < nkb) {
            issue_kv(sKV + (kb & 1) * ASTG_B, Kh, Kl, Vh, Vl, base, kb + 2, tid);
            CP_COMMIT();
        }
    }

    // ---- epilogue ----
    const float inv0 = 1.0f / l0;
    const float inv1 = 1.0f / l1;
    const int b = bh >> 4, h = bh & 15;
    const size_t row0 = (size_t)(b * SS + r0) * DM;
    const size_t row1 = (size_t)(b * SS + r1) * DM;
#pragma unroll
    for (int nj = 0; nj < 8; nj++) {
        const int e = h * 64 + nj * 8 + 2 * t;
        uint32_t uh, ul;
        split2(oacc[nj][0] * inv0, oacc[nj][1] * inv0, uh, ul);
        *(uint32_t*)&AOh[row0 + e] = uh;
        *(uint32_t*)&AOl[row0 + e] = ul;
        split2(oacc[nj][2] * inv1, oacc[nj][3] * inv1, uh, ul);
        *(uint32_t*)&AOh[row1 + e] = uh;
        *(uint32_t*)&AOl[row1 + e] = ul;
    }
}

// ---------------------------------------------------------------------------
extern "C" void kernel_launch(void* const* d_in, const int* in_sizes, int n_in,
                              void* d_out, int out_size)
{
    const float* x  = (const float*)d_in[0];
    const float* Wq = (const float*)d_in[1];
    const float* Wk = (const float*)d_in[2];
    const float* Wv = (const float*)d_in[3];
    const float* Wo = (const float*)d_in[4];
    const int*   tp = (const int*)  d_in[5];
    float* out = (float*)d_out;

    float* gRope;
    __nv_bfloat16 *xh, *xl, *wh, *wl, *aoh, *aol;
    __nv_bfloat16 *qh, *ql, *kh, *kl, *vh, *vl;
    cudaGetSymbolAddress((void**)&gRope, g_rope);
    cudaGetSymbolAddress((void**)&xh,  g_xh);
    cudaGetSymbolAddress((void**)&xl,  g_xl);
    cudaGetSymbolAddress((void**)&wh,  g_wh);
    cudaGetSymbolAddress((void**)&wl,  g_wl);
    cudaGetSymbolAddress((void**)&aoh, g_aoh);
    cudaGetSymbolAddress((void**)&aol, g_aol);
    cudaGetSymbolAddress((void**)&qh,  g_Qh);
    cudaGetSymbolAddress((void**)&ql,  g_Ql);
    cudaGetSymbolAddress((void**)&kh,  g_Kh);
    cudaGetSymbolAddress((void**)&kl,  g_Kl);
    cudaGetSymbolAddress((void**)&vh,  g_Vh);
    cudaGetSymbolAddress((void**)&vl,  g_Vl);

    cudaFuncSetAttribute(gemm_mma, cudaFuncAttributeMaxDynamicSharedMemorySize, GSMEM);
    cudaFuncSetAttribute(attn_mma, cudaFuncAttributeMaxDynamicSharedMemorySize, ASMEM);

    const int nx4 = MTOT * DM / 4;
    const int nw4 = DM * DM / 4;
    split_kernel<<<nx4 / 256, 256>>>(x, xh, xl, nx4);
    dim3 wgrid(nw4 / 256, 4);
    split_w_kernel<<<wgrid, 256>>>(Wq, Wk, Wv, Wo, wh, wl);
    rope_init_kernel<<<SS * 32 / 256, 256>>>(tp, gRope);

    dim3 qkvgrid(MTOT / 128, 24);
    gemm_mma<<<qkvgrid, 256, GSMEM>>>(xh, xl, wh, wl, nullptr,
                                      qh, ql, kh, kl, vh, vl, gRope, 0);

    attn_mma<<<1024, 256, ASMEM>>>(qh, ql, kh, kl, vh, vl, aoh, aol);

    dim3 wogrid(MTOT / 128, 8);
    gemm_mma<<<wogrid, 256, GSMEM>>>(aoh, aol, wh, wl, out,
                                     qh, ql, kh, kl, vh, vl, gRope, 1);
}

// round 7
// speedup vs baseline: 2.9308x; 1.0060x over previous
#include <cuda_runtime.h>
#include <cuda_bf16.h>
#include <math.h>
#include <math_constants.h>
#include <cstdint>

#define BB 4
#define SS 2048
#define DM 1024
#define HH 16
#define DKK 64
#define MTOT (BB*SS)   // 8192

// ---------------- scratch (allocation-free) ----------------
__device__ __nv_bfloat16 g_xh[(size_t)MTOT*DM],  g_xl[(size_t)MTOT*DM];
__device__ __nv_bfloat16 g_aoh[(size_t)MTOT*DM], g_aol[(size_t)MTOT*DM];
__device__ __nv_bfloat16 g_wh[(size_t)4*DM*DM],  g_wl[(size_t)4*DM*DM];
__device__ __nv_bfloat16 g_Qh[(size_t)BB*HH*SS*DKK], g_Ql[(size_t)BB*HH*SS*DKK];
__device__ __nv_bfloat16 g_Kh[(size_t)BB*HH*SS*DKK], g_Kl[(size_t)BB*HH*SS*DKK];
__device__ __nv_bfloat16 g_Vh[(size_t)BB*HH*SS*DKK], g_Vl[(size_t)BB*HH*SS*DKK];
__device__ float g_rope[SS*64];   // [s][0..31]=cos, [s][32..63]=sin

#define ASCALE 0.1803368801111244f   // 1/sqrt(64)*log2(e)

// ---------------- PTX helpers ----------------
__device__ __forceinline__ uint32_t smem_to_u32(const void* p) {
    uint32_t a;
    asm("{ .reg .u64 t; cvta.to.shared.u64 t, %1; cvt.u32.u64 %0, t; }"
        : "=r"(a) : "l"(p));
    return a;
}
__device__ __forceinline__ void cp16(uint32_t dst, const void* src) {
    asm volatile("cp.async.cg.shared.global [%0], [%1], 16;"
                 :: "r"(dst), "l"(src) : "memory");
}
#define CP_COMMIT() asm volatile("cp.async.commit_group;" ::: "memory")
#define CP_WAIT1()  asm volatile("cp.async.wait_group 1;"  ::: "memory")
#define CP_WAIT0()  asm volatile("cp.async.wait_group 0;"  ::: "memory")

__device__ __forceinline__ void ldsm4(uint32_t* r, uint32_t addr) {
    asm volatile("ldmatrix.sync.aligned.m8n8.x4.shared.b16 {%0,%1,%2,%3}, [%4];"
                 : "=r"(r[0]), "=r"(r[1]), "=r"(r[2]), "=r"(r[3]) : "r"(addr));
}
__device__ __forceinline__ void ldsm4t(uint32_t* r, uint32_t addr) {
    asm volatile("ldmatrix.sync.aligned.m8n8.x4.trans.shared.b16 {%0,%1,%2,%3}, [%4];"
                 : "=r"(r[0]), "=r"(r[1]), "=r"(r[2]), "=r"(r[3]) : "r"(addr));
}
__device__ __forceinline__ void mma16816(float* d, const uint32_t* a,
                                         uint32_t b0, uint32_t b1) {
    asm volatile("mma.sync.aligned.m16n8k16.row.col.f32.bf16.bf16.f32 "
                 "{%0,%1,%2,%3}, {%4,%5,%6,%7}, {%8,%9}, {%0,%1,%2,%3};"
                 : "+f"(d[0]), "+f"(d[1]), "+f"(d[2]), "+f"(d[3])
                 : "r"(a[0]), "r"(a[1]), "r"(a[2]), "r"(a[3]), "r"(b0), "r"(b1));
}
__device__ __forceinline__ float ex2(float x) {
    float y;
    asm("ex2.approx.f32 %0, %1;" : "=f"(y) : "f"(x));
    return y;
}
__device__ __forceinline__ uint32_t packbf(float lo, float hi) {
    uint32_t r;
    asm("cvt.rn.bf16x2.f32 %0, %1, %2;" : "=r"(r) : "f"(hi), "f"(lo));
    return r;
}
__device__ __forceinline__ void split2(float d0, float d1, uint32_t& uh, uint32_t& ul) {
    uh = packbf(d0, d1);
    float h0 = __uint_as_float(uh << 16);
    float h1 = __uint_as_float(uh & 0xffff0000u);
    ul = packbf(d0 - h0, d1 - h1);
}

// ---------------------------------------------------------------------------
// fp32 -> (bf16 hi, bf16 lo) splits
// ---------------------------------------------------------------------------
__global__ void split_kernel(const float* __restrict__ src,
                             __nv_bfloat16* __restrict__ hi,
                             __nv_bfloat16* __restrict__ lo, int n4)
{
    int i = blockIdx.x * blockDim.x + threadIdx.x;
    if (i >= n4) return;
    float4 v = ((const float4*)src)[i];
    uint32_t h0, l0, h1, l1;
    split2(v.x, v.y, h0, l0);
    split2(v.z, v.w, h1, l1);
    ((uint2*)hi)[i] = make_uint2(h0, h1);
    ((uint2*)lo)[i] = make_uint2(l0, l1);
}

__global__ void split_w_kernel(const float* __restrict__ w0, const float* __restrict__ w1,
                               const float* __restrict__ w2, const float* __restrict__ w3,
                               __nv_bfloat16* __restrict__ hi,
                               __nv_bfloat16* __restrict__ lo)
{
    const int wsel = blockIdx.y;
    const float* src = (wsel == 0) ? w0 : (wsel == 1) ? w1 : (wsel == 2) ? w2 : w3;
    size_t off = (size_t)wsel * (DM * DM / 4);
    int i = blockIdx.x * blockDim.x + threadIdx.x;
    float4 v = ((const float4*)src)[i];
    uint32_t h0, l0, h1, l1;
    split2(v.x, v.y, h0, l0);
    split2(v.z, v.w, h1, l1);
    ((uint2*)hi)[off + i] = make_uint2(h0, h1);
    ((uint2*)lo)[off + i] = make_uint2(l0, l1);
}

__global__ void rope_init_kernel(const int* __restrict__ tokpos, float* __restrict__ rope)
{
    int idx = blockIdx.x * blockDim.x + threadIdx.x;
    int s = idx >> 5, p = idx & 31;
    float fr = (float)exp2(-(double)p * (13.287712379549449 / 32.0));
    float ang = (float)tokpos[s] * fr;
    float sn, cs;
    sincosf(ang, &sn, &cs);
    rope[s * 64 + p] = cs;
    rope[s * 64 + 32 + p] = sn;
}

// ---------------------------------------------------------------------------
// bf16x3 mma.sync GEMM, 2-stage, 2 CTAs/SM, term-major MMA ordering.
// ---------------------------------------------------------------------------
#define GP      40
#define TILE_B  (128*GP*2)         // 10240
#define STAGE_B (4*TILE_B)         // 40960
#define GSMEM   (2*STAGE_B)        // 81920

__device__ __forceinline__ void issue_stage(uint32_t sdst,
    const __nv_bfloat16* __restrict__ Ah, const __nv_bfloat16* __restrict__ Al,
    const __nv_bfloat16* __restrict__ Bh, const __nv_bfloat16* __restrict__ Bl,
    int m0, int n0, int kc, int tid)
{
    const int colb = kc * 64;
#pragma unroll
    for (int it = 0; it < 2; it++) {
        int idx = tid + it * 256;
        int row = idx >> 2;
        int ch  = (idx & 3) * 16;
        uint32_t soff = row * 80 + ch;
        const char* pa = (const char*)(Ah + (size_t)(m0 + row) * DM) + colb + ch;
        const char* pl = (const char*)(Al + (size_t)(m0 + row) * DM) + colb + ch;
        const char* pb = (const char*)(Bh + (size_t)(n0 + row) * DM) + colb + ch;
        const char* pc = (const char*)(Bl + (size_t)(n0 + row) * DM) + colb + ch;
        cp16(sdst + 0 * TILE_B + soff, pa);
        cp16(sdst + 1 * TILE_B + soff, pl);
        cp16(sdst + 2 * TILE_B + soff, pb);
        cp16(sdst + 3 * TILE_B + soff, pc);
    }
}

__global__ __launch_bounds__(256, 2)
void gemm_mma(const __nv_bfloat16* __restrict__ Ah, const __nv_bfloat16* __restrict__ Al,
              const __nv_bfloat16* __restrict__ WhBase, const __nv_bfloat16* __restrict__ WlBase,
              float* __restrict__ out,
              __nv_bfloat16* __restrict__ qh, __nv_bfloat16* __restrict__ ql,
              __nv_bfloat16* __restrict__ kh, __nv_bfloat16* __restrict__ kl,
              __nv_bfloat16* __restrict__ vvh, __nv_bfloat16* __restrict__ vvl,
              const float* __restrict__ rope, int wo)
{
    extern __shared__ char smc[];
    const uint32_t sbase = smem_to_u32(smc);

    const int tid  = threadIdx.x;
    const int wid  = tid >> 5;
    const int lane = tid & 31;
    const int m0 = blockIdx.x * 128;
    const int by = blockIdx.y;
    const int wsel = wo ? 3 : (by >> 3);
    const int n0 = wo ? by * 128 : (by & 7) * 128;
    const __nv_bfloat16* Bh = WhBase + (size_t)wsel * DM * DM;
    const __nv_bfloat16* Bl = WlBase + (size_t)wsel * DM * DM;

    const int wm = (wid & 3) * 32;
    const int wn = (wid >> 2) * 64;

    float acc[2][8][4];
#pragma unroll
    for (int i = 0; i < 2; i++)
#pragma unroll
        for (int j = 0; j < 8; j++)
#pragma unroll
            for (int q = 0; q < 4; q++) acc[i][j][q] = 0.f;

    const uint32_t lrow = (lane & 7) + ((lane >> 3) & 1) * 8;
    const uint32_t kbl  = ((lane >> 4) & 1) * 16;

    issue_stage(sbase, Ah, Al, Bh, Bl, m0, n0, 0, tid);
    CP_COMMIT();

    const int NKC = DM / 32;   // 32
    for (int kc = 0; kc < NKC; kc++) {
        if (kc + 1 < NKC) {
            issue_stage(sbase + ((kc + 1) & 1) * STAGE_B, Ah, Al, Bh, Bl,
                        m0, n0, kc + 1, tid);
            CP_COMMIT();
            CP_WAIT1();
        } else {
            CP_WAIT0();
        }
        __syncthreads();

        const uint32_t sb = sbase + (kc & 1) * STAGE_B;
#pragma unroll
        for (int ks = 0; ks < 2; ks++) {
            const uint32_t kb = ks * 32 + kbl;
            uint32_t ah0[4], ah1[4], al0[4], al1[4];
            const uint32_t aadr = sb + (wm + lrow) * 80 + kb;
            ldsm4(ah0, aadr);
            ldsm4(ah1, aadr + 16 * 80);
            ldsm4(al0, aadr + TILE_B);
            ldsm4(al1, aadr + TILE_B + 16 * 80);
#pragma unroll
            for (int nbp = 0; nbp < 2; nbp++) {       // pairs of 16-col tiles
                uint32_t bh[2][4], bl[2][4];
#pragma unroll
                for (int nb2 = 0; nb2 < 2; nb2++) {
                    const uint32_t badr = sb + 2 * TILE_B
                        + (wn + (nbp * 2 + nb2) * 16 + lrow) * 80 + kb;
                    ldsm4(bh[nb2], badr);
                    ldsm4(bl[nb2], badr + TILE_B);
                }
                // term-major: same-acc reuse distance = 8 MMAs
#pragma unroll
                for (int term = 0; term < 3; term++) {
                    const uint32_t* a0 = (term == 2) ? al0 : ah0;
                    const uint32_t* a1 = (term == 2) ? al1 : ah1;
#pragma unroll
                    for (int nb2 = 0; nb2 < 2; nb2++) {
#pragma unroll
                        for (int sel = 0; sel < 2; sel++) {
                            const int nj = (nbp * 2 + nb2) * 2 + sel;
                            const uint32_t b0 = (term == 1) ? bl[nb2][sel]     : bh[nb2][sel];
                            const uint32_t b1 = (term == 1) ? bl[nb2][sel + 2] : bh[nb2][sel + 2];
                            mma16816(acc[0][nj], a0, b0, b1);
                            mma16816(acc[1][nj], a1, b0, b1);
                        }
                    }
                }
            }
        }
        __syncthreads();
    }

    // ---- epilogue ----
    __nv_bfloat16 *oh = qh, *ol = ql;
    if (wsel == 1) { oh = kh; ol = kl; }
    else if (wsel == 2) { oh = vvh; ol = vvl; }

    const int g = lane >> 2;
    const int t2 = (lane & 3) * 2;
#pragma unroll
    for (int mi = 0; mi < 2; mi++) {
#pragma unroll
        for (int half = 0; half < 2; half++) {
            const int r = m0 + wm + mi * 16 + half * 8 + g;
            const int b = r >> 11;
            const int s = r & 2047;
#pragma unroll
            for (int nj = 0; nj < 8; nj++) {
                const int e = n0 + wn + nj * 8 + t2;
                float d0 = acc[mi][nj][half * 2 + 0];
                float d1 = acc[mi][nj][half * 2 + 1];
                if (wsel == 3) {
                    *(float2*)&out[(size_t)r * DM + e] = make_float2(d0, d1);
                } else {
                    const int h  = e >> 6;
                    const int dk = e & 63;
                    if (wsel <= 1) {
                        const int p = dk >> 1;
                        float cs = __ldg(&rope[s * 64 + p]);
                        float sn = __ldg(&rope[s * 64 + 32 + p]);
                        float r0 = d0 * cs - d1 * sn;
                        float r1 = d0 * sn + d1 * cs;
                        d0 = r0; d1 = r1;
                        if (wsel == 0) { d0 *= ASCALE; d1 *= ASCALE; }
                    }
                    size_t idx = ((size_t)(b * HH + h) * SS + s) * DKK + dk;
                    uint32_t uh, ul;
                    split2(d0, d1, uh, ul);
                    *(uint32_t*)&oh[idx] = uh;
                    *(uint32_t*)&ol[idx] = ul;
                }
            }
        }
    }
}

// ---------------------------------------------------------------------------
// Tensor-core flash attention (bf16x3, causal), 2-stage KV, 2 CTAs/SM,
// term-major MMA ordering.
// ---------------------------------------------------------------------------
#define AP      144
#define QT_B    (128*AP)      // 18432
#define KT_B    (64*AP)       // 9216
#define ASTG_B  (4*KT_B)      // 36864
#define ASMEM   (2*QT_B + 2*ASTG_B)   // 110592

__device__ __forceinline__ void issue_kv(uint32_t dst,
    const __nv_bfloat16* __restrict__ Kh, const __nv_bfloat16* __restrict__ Kl,
    const __nv_bfloat16* __restrict__ Vh, const __nv_bfloat16* __restrict__ Vl,
    size_t base, int kb, int tid)
{
#pragma unroll
    for (int it = 0; it < 8; it++) {
        int f   = tid + it * 256;
        int ten = f >> 9;
        int row = (f >> 3) & 63;
        int ch  = f & 7;
        const __nv_bfloat16* sp = (ten == 0) ? Kh : (ten == 1) ? Kl
                                 : (ten == 2) ? Vh : Vl;
        sp += base + (size_t)(kb * 64 + row) * DKK + ch * 8;
        cp16(dst + ten * KT_B + row * AP + ch * 16, sp);
    }
}

__global__ __launch_bounds__(256, 2)
void attn_mma(const __nv_bfloat16* __restrict__ Qh, const __nv_bfloat16* __restrict__ Ql,
              const __nv_bfloat16* __restrict__ Kh, const __nv_bfloat16* __restrict__ Kl,
              const __nv_bfloat16* __restrict__ Vh, const __nv_bfloat16* __restrict__ Vl,
              __nv_bfloat16* __restrict__ AOh, __nv_bfloat16* __restrict__ AOl)
{
    extern __shared__ char smc[];
    const uint32_t sb = smem_to_u32(smc);
    const uint32_t sQ  = sb;
    const uint32_t sKV = sb + 2 * QT_B;

    const int tid  = threadIdx.x;
    const int wid  = tid >> 5;
    const int lane = tid & 31;
    const int g = lane >> 2;
    const int t = lane & 3;

    const int qb = 15 - (blockIdx.x >> 6);    // heavy q-blocks first
    const int bh = blockIdx.x & 63;
    const size_t base = (size_t)bh * SS * DKK;
    const int nkb = 2 * qb + 2;               // >= 2

    const float NINF = __int_as_float(0xff800000);

#pragma unroll
    for (int it = 0; it < 8; it++) {
        int f   = tid + it * 256;
        int ten = f >> 10;
        int row = (f >> 3) & 127;
        int ch  = f & 7;
        const __nv_bfloat16* sp = (ten ? Ql : Qh)
            + base + (size_t)(qb * 128 + row) * DKK + ch * 8;
        cp16(sQ + ten * QT_B + row * AP + ch * 16, sp);
    }
    issue_kv(sKV, Kh, Kl, Vh, Vl, base, 0, tid);
    CP_COMMIT();
    issue_kv(sKV + ASTG_B, Kh, Kl, Vh, Vl, base, 1, tid);
    CP_COMMIT();

    CP_WAIT1();            // group 0 (Q + KV0) complete
    __syncthreads();

    const uint32_t lrow = (lane & 7) + ((lane >> 3) & 1) * 8;
    const uint32_t kb16 = ((lane >> 4) & 1) * 16;
    uint32_t qfh[4][4], qfl[4][4];
#pragma unroll
    for (int ks = 0; ks < 4; ks++) {
        uint32_t a = sQ + (wid * 16 + lrow) * AP + ks * 32 + kb16;
        ldsm4(qfh[ks], a);
        ldsm4(qfl[ks], a + QT_B);
    }

    float oacc[8][4];
#pragma unroll
    for (int nj = 0; nj < 8; nj++)
#pragma unroll
        for (int q = 0; q < 4; q++) oacc[nj][q] = 0.f;
    float m0 = NINF, m1 = NINF, l0 = 0.f, l1 = 0.f;

    const int r0 = qb * 128 + wid * 16 + g;
    const int r1 = r0 + 8;

    const uint32_t vrow = (lane & 7) + ((lane >> 4) & 1) * 8;
    const uint32_t vb16 = ((lane >> 3) & 1) * 16;

    for (int kb = 0; kb < nkb; kb++) {
        if (kb + 1 < nkb) CP_WAIT1(); else CP_WAIT0();
        __syncthreads();

        const uint32_t sK = sKV + (kb & 1) * ASTG_B;
        const uint32_t sV = sK + 2 * KT_B;

        // ---- S = Qh*Kh + Qh*Kl + Ql*Kh (term-major per nt-pair) ----
        float sf[8][4];
#pragma unroll
        for (int nj = 0; nj < 8; nj++)
#pragma unroll
            for (int q = 0; q < 4; q++) sf[nj][q] = 0.f;

#pragma unroll
        for (int ks = 0; ks < 4; ks++) {
#pragma unroll
            for (int ntp = 0; ntp < 2; ntp++) {
                uint32_t kfh[2][4], kfl[2][4];
#pragma unroll
                for (int nt2 = 0; nt2 < 2; nt2++) {
                    uint32_t ba = sK + ((ntp * 2 + nt2) * 16 + lrow) * AP + ks * 32 + kb16;
                    ldsm4(kfh[nt2], ba);
                    ldsm4(kfl[nt2], ba + KT_B);
                }
#pragma unroll
                for (int term = 0; term < 3; term++) {
                    const uint32_t* a = (term == 2) ? qfl[ks] : qfh[ks];
#pragma unroll
                    for (int nt2 = 0; nt2 < 2; nt2++) {
#pragma unroll
                        for (int sel = 0; sel < 2; sel++) {
                            const int nj = (ntp * 2 + nt2) * 2 + sel;
                            const uint32_t b0 = (term == 1) ? kfl[nt2][sel]     : kfh[nt2][sel];
                            const uint32_t b1 = (term == 1) ? kfl[nt2][sel + 2] : kfh[nt2][sel + 2];
                            mma16816(sf[nj], a, b0, b1);
                        }
                    }
                }
            }
        }

        // ---- causal mask ----
        if (kb >= 2 * qb) {
#pragma unroll
            for (int nj = 0; nj < 8; nj++) {
                int c0 = kb * 64 + nj * 8 + 2 * t;
                if (c0 > r0)     sf[nj][0] = NINF;
                if (c0 + 1 > r0) sf[nj][1] = NINF;
                if (c0 > r1)     sf[nj][2] = NINF;
                if (c0 + 1 > r1) sf[nj][3] = NINF;
            }
        }

        // ---- online softmax (base-2 domain) ----
        float mx0 = sf[0][0], mx1 = sf[0][2];
#pragma unroll
        for (int nj = 0; nj < 8; nj++) {
            mx0 = fmaxf(mx0, fmaxf(sf[nj][0], sf[nj][1]));
            mx1 = fmaxf(mx1, fmaxf(sf[nj][2], sf[nj][3]));
        }
        mx0 = fmaxf(mx0, __shfl_xor_sync(0xffffffffu, mx0, 1));
        mx0 = fmaxf(mx0, __shfl_xor_sync(0xffffffffu, mx0, 2));
        mx1 = fmaxf(mx1, __shfl_xor_sync(0xffffffffu, mx1, 1));
        mx1 = fmaxf(mx1, __shfl_xor_sync(0xffffffffu, mx1, 2));
        float mn0 = fmaxf(m0, mx0), mn1 = fmaxf(m1, mx1);
        float al0 = ex2(m0 - mn0), al1 = ex2(m1 - mn1);
        m0 = mn0; m1 = mn1;

        float s0 = 0.f, s1 = 0.f;
#pragma unroll
        for (int nj = 0; nj < 8; nj++) {
            sf[nj][0] = ex2(sf[nj][0] - m0);
            sf[nj][1] = ex2(sf[nj][1] - m0);
            sf[nj][2] = ex2(sf[nj][2] - m1);
            sf[nj][3] = ex2(sf[nj][3] - m1);
            s0 += sf[nj][0] + sf[nj][1];
            s1 += sf[nj][2] + sf[nj][3];
        }
        s0 += __shfl_xor_sync(0xffffffffu, s0, 1);
        s0 += __shfl_xor_sync(0xffffffffu, s0, 2);
        s1 += __shfl_xor_sync(0xffffffffu, s1, 1);
        s1 += __shfl_xor_sync(0xffffffffu, s1, 2);
        l0 = l0 * al0 + s0;
        l1 = l1 * al1 + s1;

#pragma unroll
        for (int nj = 0; nj < 8; nj++) {
            oacc[nj][0] *= al0; oacc[nj][1] *= al0;
            oacc[nj][2] *= al1; oacc[nj][3] *= al1;
        }

        // ---- O += Ph*Vh + Ph*Vl + Pl*Vh (term-major per nt-pair) ----
#pragma unroll
        for (int ks = 0; ks < 4; ks++) {
            uint32_t pah[4], pal[4];
            split2(sf[2 * ks][0],     sf[2 * ks][1],     pah[0], pal[0]);
            split2(sf[2 * ks][2],     sf[2 * ks][3],     pah[1], pal[1]);
            split2(sf[2 * ks + 1][0], sf[2 * ks + 1][1], pah[2], pal[2]);
            split2(sf[2 * ks + 1][2], sf[2 * ks + 1][3], pah[3], pal[3]);
#pragma unroll
            for (int ntp = 0; ntp < 2; ntp++) {
                uint32_t vfh[2][4], vfl[2][4];
#pragma unroll
                for (int nt2 = 0; nt2 < 2; nt2++) {
                    uint32_t va = sV + (ks * 16 + vrow) * AP + (ntp * 2 + nt2) * 32 + vb16;
                    ldsm4t(vfh[nt2], va);
                    ldsm4t(vfl[nt2], va + KT_B);
                }
#pragma unroll
                for (int term = 0; term < 3; term++) {
                    const uint32_t* a = (term == 2) ? pal : pah;
#pragma unroll
                    for (int nt2 = 0; nt2 < 2; nt2++) {
#pragma unroll
                        for (int sel = 0; sel < 2; sel++) {
                            const int nj = (ntp * 2 + nt2) * 2 + sel;
                            const uint32_t b0 = (term == 1) ? vfl[nt2][sel]     : vfh[nt2][sel];
                            const uint32_t b1 = (term == 1) ? vfl[nt2][sel + 2] : vfh[nt2][sel + 2];
                            mma16816(oacc[nj], a, b0, b1);
                        }
                    }
                }
            }
        }
        __syncthreads();

        if (kb + 2 < nkb) {
            issue_kv(sKV + (kb & 1) * ASTG_B, Kh, Kl, Vh, Vl, base, kb + 2, tid);
            CP_COMMIT();
        }
    }

    // ---- epilogue ----
    const float inv0 = 1.0f / l0;
    const float inv1 = 1.0f / l1;
    const int b = bh >> 4, h = bh & 15;
    const size_t row0 = (size_t)(b * SS + r0) * DM;
    const size_t row1 = (size_t)(b * SS + r1) * DM;
#pragma unroll
    for (int nj = 0; nj < 8; nj++) {
        const int e = h * 64 + nj * 8 + 2 * t;
        uint32_t uh, ul;
        split2(oacc[nj][0] * inv0, oacc[nj][1] * inv0, uh, ul);
        *(uint32_t*)&AOh[row0 + e] = uh;
        *(uint32_t*)&AOl[row0 + e] = ul;
        split2(oacc[nj][2] * inv1, oacc[nj][3] * inv1, uh, ul);
        *(uint32_t*)&AOh[row1 + e] = uh;
        *(uint32_t*)&AOl[row1 + e] = ul;
    }
}

// ---------------------------------------------------------------------------
extern "C" void kernel_launch(void* const* d_in, const int* in_sizes, int n_in,
                              void* d_out, int out_size)
{
    const float* x  = (const float*)d_in[0];
    const float* Wq = (const float*)d_in[1];
    const float* Wk = (const float*)d_in[2];
    const float* Wv = (const float*)d_in[3];
    const float* Wo = (const float*)d_in[4];
    const int*   tp = (const int*)  d_in[5];
    float* out = (float*)d_out;

    float* gRope;
    __nv_bfloat16 *xh, *xl, *wh, *wl, *aoh, *aol;
    __nv_bfloat16 *qh, *ql, *kh, *kl, *vh, *vl;
    cudaGetSymbolAddress((void**)&gRope, g_rope);
    cudaGetSymbolAddress((void**)&xh,  g_xh);
    cudaGetSymbolAddress((void**)&xl,  g_xl);
    cudaGetSymbolAddress((void**)&wh,  g_wh);
    cudaGetSymbolAddress((void**)&wl,  g_wl);
    cudaGetSymbolAddress((void**)&aoh, g_aoh);
    cudaGetSymbolAddress((void**)&aol, g_aol);
    cudaGetSymbolAddress((void**)&qh,  g_Qh);
    cudaGetSymbolAddress((void**)&ql,  g_Ql);
    cudaGetSymbolAddress((void**)&kh,  g_Kh);
    cudaGetSymbolAddress((void**)&kl,  g_Kl);
    cudaGetSymbolAddress((void**)&vh,  g_Vh);
    cudaGetSymbolAddress((void**)&vl,  g_Vl);

    cudaFuncSetAttribute(gemm_mma, cudaFuncAttributeMaxDynamicSharedMemorySize, GSMEM);
    cudaFuncSetAttribute(attn_mma, cudaFuncAttributeMaxDynamicSharedMemorySize, ASMEM);

    const int nx4 = MTOT * DM / 4;
    const int nw4 = DM * DM / 4;
    split_kernel<<<nx4 / 256, 256>>>(x, xh, xl, nx4);
    dim3 wgrid(nw4 / 256, 4);
    split_w_kernel<<<wgrid, 256>>>(Wq, Wk, Wv, Wo, wh, wl);
    rope_init_kernel<<<SS * 32 / 256, 256>>>(tp, gRope);

    dim3 qkvgrid(MTOT / 128, 24);
    gemm_mma<<<qkvgrid, 256, GSMEM>>>(xh, xl, wh, wl, nullptr,
                                      qh, ql, kh, kl, vh, vl, gRope, 0);

    attn_mma<<<1024, 256, ASMEM>>>(qh, ql, kh, kl, vh, vl, aoh, aol);

    dim3 wogrid(MTOT / 128, 8);
    gemm_mma<<<wogrid, 256, GSMEM>>>(aoh, aol, wh, wl, out,
                                     qh, ql, kh, kl, vh, vl, gRope, 1);
}